// round 14
// baseline (speedup 1.0000x reference)
#include <cuda_runtime.h>
#include <cuda_fp16.h>
#include <stdint.h>
#include <math.h>

#define SQ      2048
#define DMODEL  4096
#define DHEAD   128
#define NHEADS  32
#define NKV     8
#define KDIM_Q  (NHEADS*DHEAD)   /* 4096 */
#define KDIM_KV (NKV*DHEAD)      /* 1024 */
#define NQKV    (KDIM_Q + 2*KDIM_KV)  /* 6144 */
#define QS      (0.08838834764831845f * 1.44269504088896341f)  /* 1/sqrt(128) * log2(e) */

// -------- scratch (device globals: allocation-free) --------
__device__ __align__(256) __half g_h16[SQ*DMODEL];
__device__ __align__(256) __half g_wqkv16[NQKV*DMODEL];
__device__ __align__(256) __half g_wo16[DMODEL*DMODEL];
__device__ __align__(256) __half g_qkv16[SQ*NQKV];
__device__ __align__(256) __half g_attn16[SQ*DMODEL];

// ============================ helpers ============================
static __device__ __forceinline__ uint32_t smem_u32(const void* p) {
    uint32_t a;
    asm("{ .reg .u64 t; cvta.to.shared.u64 t, %1; cvt.u32.u64 %0, t; }" : "=r"(a) : "l"(p));
    return a;
}
static __device__ __forceinline__ float ex2f(float x) {
    float y; asm("ex2.approx.ftz.f32 %0, %1;" : "=f"(y) : "f"(x)); return y;
}
#define SWZ128(x) ((x) ^ (((x) >> 3) & 0x70))

#define CP16(s, g) \
    asm volatile("cp.async.cg.shared.global [%0], [%1], 16;" :: "r"(s), "l"(g) : "memory")
#define CP_COMMIT() asm volatile("cp.async.commit_group;" ::: "memory")
#define CP_WAIT0()  asm volatile("cp.async.wait_group 0;" ::: "memory")
#define CP_WAIT1()  asm volatile("cp.async.wait_group 1;" ::: "memory")

#define LDSM_X4(r0,r1,r2,r3,addr) \
    asm volatile("ldmatrix.sync.aligned.m8n8.x4.shared.b16 {%0,%1,%2,%3}, [%4];" \
        : "=r"(r0),"=r"(r1),"=r"(r2),"=r"(r3) : "r"(addr))
#define LDSM_X4T(r0,r1,r2,r3,addr) \
    asm volatile("ldmatrix.sync.aligned.m8n8.x4.trans.shared.b16 {%0,%1,%2,%3}, [%4];" \
        : "=r"(r0),"=r"(r1),"=r"(r2),"=r"(r3) : "r"(addr))

#define MMA16816(d, a, b) \
    asm volatile("mma.sync.aligned.m16n8k16.row.col.f32.f16.f16.f32 " \
        "{%0,%1,%2,%3}, {%4,%5,%6,%7}, {%8,%9}, {%0,%1,%2,%3};" \
        : "+f"((d)[0]),"+f"((d)[1]),"+f"((d)[2]),"+f"((d)[3]) \
        : "r"((a)[0]),"r"((a)[1]),"r"((a)[2]),"r"((a)[3]), "r"((b)[0]),"r"((b)[1]))

// ============================ fused prep: weight cvt + RMSNorm ============================
#define CVT_N4   ((KDIM_Q*DMODEL + 2*KDIM_KV*DMODEL + DMODEL*DMODEL) / 4)
#define NCVT     (CVT_N4 / 256)

__global__ __launch_bounds__(256) void prep_kernel(
    const float4* __restrict__ wq, const float4* __restrict__ wk,
    const float4* __restrict__ wv, const float4* __restrict__ wo,
    __half2* __restrict__ wqkv, __half2* __restrict__ wo16,
    const float* __restrict__ x, const float* __restrict__ nw, __half* __restrict__ h)
{
    if (blockIdx.x < NCVT) {
        int i = blockIdx.x * 256 + threadIdx.x;
        const int A = KDIM_Q*DMODEL/4;
        const int B = A + KDIM_KV*DMODEL/4;
        const int C = B + KDIM_KV*DMODEL/4;
        float4 v; __half2* o;
        if (i < A)      { v = wq[i];     o = wqkv + 2*(size_t)i; }
        else if (i < B) { v = wk[i-A];   o = wqkv + 2*(size_t)i; }
        else if (i < C) { v = wv[i-B];   o = wqkv + 2*(size_t)i; }
        else            { v = wo[i-C];   o = wo16 + 2*(size_t)(i-C); }
        o[0] = __floats2half2_rn(v.x, v.y);
        o[1] = __floats2half2_rn(v.z, v.w);
        return;
    }
    int row = blockIdx.x - NCVT;
    const float* xr = x + (size_t)row * DMODEL;
    float ss = 0.f;
    for (int i = threadIdx.x; i < DMODEL/4; i += blockDim.x) {
        float4 v = ((const float4*)xr)[i];
        ss += v.x*v.x + v.y*v.y + v.z*v.z + v.w*v.w;
    }
    __shared__ float red[32];
    #pragma unroll
    for (int o = 16; o > 0; o >>= 1) ss += __shfl_xor_sync(0xffffffffu, ss, o);
    if ((threadIdx.x & 31) == 0) red[threadIdx.x >> 5] = ss;
    __syncthreads();
    if (threadIdx.x < 32) {
        float v = (threadIdx.x < 8) ? red[threadIdx.x] : 0.f;
        #pragma unroll
        for (int o = 16; o > 0; o >>= 1) v += __shfl_xor_sync(0xffffffffu, v, o);
        if (threadIdx.x == 0) red[0] = v;
    }
    __syncthreads();
    float scale = rsqrtf(red[0] / (float)DMODEL + 1e-5f);
    __half2* hr = (__half2*)(h + (size_t)row * DMODEL);
    for (int i = threadIdx.x; i < DMODEL/4; i += blockDim.x) {
        float4 v  = ((const float4*)xr)[i];
        float4 wv = ((const float4*)nw)[i];
        hr[2*i+0] = __floats2half2_rn(v.x*scale*wv.x, v.y*scale*wv.y);
        hr[2*i+1] = __floats2half2_rn(v.z*scale*wv.z, v.w*scale*wv.w);
    }
}

// ============================ persistent HMMA HGEMM ============================
// 128x128 tiles, 3-stage cp.async ring, 2 CTA/SM, single sync per K-iteration.
// Persistent: gridDim.x CTAs loop over all output tiles (kills wave quantization).
#define HG_STAGE 32768
#define HG_SMEM  (3*HG_STAGE)
#define HG_GRID  304   /* 2 per SM x 152 SMs */

template<typename OutT>
__global__ __launch_bounds__(256, 2) void hgemm_mma(
    const __half* __restrict__ A, const __half* __restrict__ B,
    OutT* __restrict__ C, const float* __restrict__ R,
    int M, int N, int K, int ldC, int ntx, int ntiles,
    const float* __restrict__ rc, const float* __restrict__ rs)
{
    extern __shared__ char sm[];
    const uint32_t sb = smem_u32(sm);
    const int tid  = threadIdx.x;
    const int lane = tid & 31;
    const int wid  = tid >> 5;
    const int wm   = wid & 1;
    const int wn   = wid >> 1;

    const int lrow = tid >> 3;
    const int lch  = tid & 7;
    uint32_t swoff[4];
    #pragma unroll
    for (int j = 0; j < 4; j++)
        swoff[j] = SWZ128((uint32_t)((lrow + 32*j)*128 + lch*16));

    const uint32_t a_row0 = (uint32_t)(wm*64 + (lane & 15)) * 128;
    const uint32_t a_csel = (uint32_t)(lane >> 4) * 16;
    const uint32_t b_row0 = (uint32_t)(wn*32 + ((lane >> 4) & 1)*8 + (lane & 7)) * 128;
    const uint32_t b_csel = (uint32_t)((lane >> 3) & 1) * 16;

    const int nk = K >> 6;

    for (int t = blockIdx.x; t < ntiles; t += gridDim.x) {
        const int bm = (t / ntx) * 128;
        const int bn = (t % ntx) * 128;
        const __half* Agp = A + (size_t)bm * K;
        const __half* Bgp = B + (size_t)bn * K;

        // drain ring + protect smem slots from previous tile's readers
        CP_WAIT0();
        __syncthreads();

        float acc[4][4][4];
        #pragma unroll
        for (int im = 0; im < 4; im++)
            #pragma unroll
            for (int in = 0; in < 4; in++)
                #pragma unroll
                for (int r = 0; r < 4; r++) acc[im][in][r] = 0.f;

        // prologue: stages 0 and 1
        #pragma unroll
        for (int s = 0; s < 2; s++) {
            uint32_t ab = sb + s*HG_STAGE, bb = ab + 16384;
            const int k0 = s << 6;
            #pragma unroll
            for (int j = 0; j < 4; j++) {
                const size_t go = (size_t)(lrow + 32*j) * K + k0 + lch*8;
                CP16(ab + swoff[j], Agp + go);
                CP16(bb + swoff[j], Bgp + go);
            }
            CP_COMMIT();
        }

        int sidx = 0;
        for (int i = 0; i < nk; i++) {
            CP_WAIT1();
            __syncthreads();

            if (i + 2 < nk) {
                int tb = sidx + 2; if (tb >= 3) tb -= 3;
                uint32_t ab = sb + tb*HG_STAGE, bb = ab + 16384;
                const int k0 = (i+2) << 6;
                #pragma unroll
                for (int j = 0; j < 4; j++) {
                    const size_t go = (size_t)(lrow + 32*j) * K + k0 + lch*8;
                    CP16(ab + swoff[j], Agp + go);
                    CP16(bb + swoff[j], Bgp + go);
                }
            }
            CP_COMMIT();

            const uint32_t As = sb + sidx*HG_STAGE;
            const uint32_t Bs = As + 16384;

            #pragma unroll
            for (int ks = 0; ks < 4; ks++) {
                uint32_t af[4][4], bf[4][2];
                #pragma unroll
                for (int im = 0; im < 4; im++) {
                    uint32_t off = SWZ128(a_row0 + (uint32_t)(im*2048) + ks*32 + a_csel);
                    LDSM_X4(af[im][0], af[im][1], af[im][2], af[im][3], As + off);
                }
                #pragma unroll
                for (int ntp = 0; ntp < 2; ntp++) {
                    uint32_t r0, r1, r2, r3;
                    uint32_t off = SWZ128(b_row0 + (uint32_t)(ntp*16*128) + ks*32 + b_csel);
                    LDSM_X4(r0, r1, r2, r3, Bs + off);
                    bf[2*ntp][0] = r0;  bf[2*ntp][1] = r1;
                    bf[2*ntp+1][0] = r2; bf[2*ntp+1][1] = r3;
                }
                #pragma unroll
                for (int im = 0; im < 4; im++)
                    #pragma unroll
                    for (int in = 0; in < 4; in++)
                        MMA16816(acc[im][in], af[im], bf[in]);
            }
            if (++sidx == 3) sidx = 0;
        }

        const bool dorope = (rc != nullptr) && (bn < KDIM_Q + KDIM_KV);
        const bool doq    = (bn < KDIM_Q);

        #pragma unroll
        for (int im = 0; im < 4; im++) {
            const int ro0 = bm + wm*64 + im*16 + (lane >> 2);
            const int ro1 = ro0 + 8;
            #pragma unroll
            for (int in = 0; in < 4; in++) {
                const int col = bn + wn*32 + in*8 + (lane & 3)*2;
                float a0 = acc[im][in][0], a1 = acc[im][in][1];
                float a2 = acc[im][in][2], a3 = acc[im][in][3];
                if (sizeof(OutT) == 2) {
                    if (dorope) {
                        int dcol = col & 127;
                        float c0 = rc[(size_t)ro0*DHEAD + dcol], s0 = rs[(size_t)ro0*DHEAD + dcol];
                        float c1 = rc[(size_t)ro1*DHEAD + dcol], s1 = rs[(size_t)ro1*DHEAD + dcol];
                        float y0 = a0*c0 - a1*s0, y1 = a1*c0 + a0*s0;
                        float y2 = a2*c1 - a3*s1, y3 = a3*c1 + a2*s1;
                        if (doq) { y0 *= QS; y1 *= QS; y2 *= QS; y3 *= QS; }
                        a0 = y0; a1 = y1; a2 = y2; a3 = y3;
                    }
                    *(__half2*)((__half*)C + (size_t)ro0*ldC + col) = __floats2half2_rn(a0, a1);
                    *(__half2*)((__half*)C + (size_t)ro1*ldC + col) = __floats2half2_rn(a2, a3);
                } else {
                    float2 v0 = make_float2(a0, a1);
                    float2 v1 = make_float2(a2, a3);
                    if (R) {
                        const float2 q0 = *(const float2*)&R[(size_t)ro0*ldC + col];
                        const float2 q1 = *(const float2*)&R[(size_t)ro1*ldC + col];
                        v0.x += q0.x; v0.y += q0.y;
                        v1.x += q1.x; v1.y += q1.y;
                    }
                    *(float2*)((float*)C + (size_t)ro0*ldC + col) = v0;
                    *(float2*)((float*)C + (size_t)ro1*ldC + col) = v1;
                }
            }
        }
    }
}

// ============================ HMMA flash attention (causal GQA, pipelined, 2 CTA/SM) ============================
#define FA_Q    0
#define FA_KV   16384
#define FA_STG  32768
#define FA_SMEM (FA_KV + 3*FA_STG)   /* 112 KB */

__global__ __launch_bounds__(128) void attn_mma(
    const __half* __restrict__ qkv, __half* __restrict__ out)
{
    extern __shared__ char sm[];
    const uint32_t sb = smem_u32(sm);
    const int tid  = threadIdx.x;
    const int lane = tid & 31;
    const int wid  = tid >> 5;

    const int head = blockIdx.y;
    const int kvh  = head >> 2;
    const int qt   = gridDim.x - 1 - blockIdx.x;

    const int lch  = tid & 7;
    const int lr16 = tid >> 3;

    const __half* qg  = qkv + (size_t)(qt*64)*NQKV + head*DHEAD;
    const __half* kg0 = qkv + KDIM_Q + kvh*DHEAD;
    const __half* vg0 = qkv + KDIM_Q + KDIM_KV + kvh*DHEAD;

    const int nkv = qt + 1;

    uint32_t stP = sb + FA_KV + 2*FA_STG;
    uint32_t stC = sb + FA_KV + 0*FA_STG;
    uint32_t stN = sb + FA_KV + 1*FA_STG;
#define FA_ROT() do { uint32_t t_ = stP; stP = stC; stC = stN; stN = t_; } while (0)

#define FA_ISSUE(T, BASE) do { \
    const __half* kg_ = kg0 + (size_t)((T)*64)*NQKV; \
    const __half* vg_ = vg0 + (size_t)((T)*64)*NQKV; \
    _Pragma("unroll") for (int p_ = 0; p_ < 2; p_++) \
    _Pragma("unroll") for (int j_ = 0; j_ < 4; j_++) { \
        int row_ = j_*16 + lr16; \
        uint32_t so_ = SWZ128((uint32_t)(row_*128 + lch*16)); \
        CP16((BASE) + p_*8192 + so_,         kg_ + (size_t)row_*NQKV + p_*64 + lch*8); \
        CP16((BASE) + 16384 + p_*8192 + so_, vg_ + (size_t)row_*NQKV + p_*64 + lch*8); \
    } \
} while (0)

    #pragma unroll
    for (int p = 0; p < 2; p++)
        #pragma unroll
        for (int j = 0; j < 4; j++) {
            int row = j*16 + lr16;
            CP16(sb + FA_Q + p*8192 + SWZ128((uint32_t)(row*128 + lch*16)),
                 qg + (size_t)row*NQKV + p*64 + lch*8);
        }
    FA_ISSUE(0, stC);
    CP_COMMIT();
    CP_WAIT0();
    __syncthreads();

    uint32_t qf[8][4];
    {
        const uint32_t rowb = (uint32_t)(wid*16 + (lane & 15)) * 128;
        const uint32_t csel = (uint32_t)(lane >> 4) * 16;
        #pragma unroll
        for (int ks = 0; ks < 8; ks++) {
            uint32_t addr = sb + FA_Q + (ks >> 2)*8192 + SWZ128(rowb + (ks & 3)*32 + csel);
            LDSM_X4(qf[ks][0], qf[ks][1], qf[ks][2], qf[ks][3], addr);
        }
    }

    float of[16][4];
    #pragma unroll
    for (int t = 0; t < 16; t++)
        #pragma unroll
        for (int r = 0; r < 4; r++) of[t][r] = 0.f;
    float m0 = -1e30f, m1 = -1e30f, l0 = 0.f, l1 = 0.f;
    float sfA[8][4], sfB[8][4];

    const int rg0 = qt*64 + wid*16 + (lane >> 2);
    const uint32_t k_row0 = (uint32_t)(((lane >> 4) & 1)*8 + (lane & 7)) * 128;
    const uint32_t k_csel = (uint32_t)((lane >> 3) & 1) * 16;
    const uint32_t v_rsel = (uint32_t)(lane & 15) * 128;
    const uint32_t v_csel = (uint32_t)(lane >> 4) * 16;

#define FA_SMM(SF, KB) do { \
    _Pragma("unroll") for (int nt_ = 0; nt_ < 8; nt_++) \
        _Pragma("unroll") for (int r_ = 0; r_ < 4; r_++) (SF)[nt_][r_] = 0.f; \
    _Pragma("unroll") for (int ks_ = 0; ks_ < 8; ks_++) { \
        const uint32_t pb_ = (KB) + (ks_ >> 2)*8192; \
        const uint32_t co_ = (ks_ & 3)*32 + k_csel; \
        _Pragma("unroll") for (int ntp_ = 0; ntp_ < 4; ntp_++) { \
            uint32_t x0_, x1_, x2_, x3_; \
            LDSM_X4(x0_, x1_, x2_, x3_, pb_ + SWZ128(k_row0 + (uint32_t)(ntp_*2048) + co_)); \
            uint32_t bA_[2] = {x0_, x1_}, bB_[2] = {x2_, x3_}; \
            MMA16816((SF)[2*ntp_],   qf[ks_], bA_); \
            MMA16816((SF)[2*ntp_+1], qf[ks_], bB_); \
        } \
    } \
} while (0)

#define FA_SMPV(SF, T, VB) do { \
    const bool diag_ = (T) == qt; \
    float mx0_ = -1e30f, mx1_ = -1e30f; \
    _Pragma("unroll") for (int nt_ = 0; nt_ < 8; nt_++) { \
        float s0_ = (SF)[nt_][0], s1_ = (SF)[nt_][1]; \
        float s2_ = (SF)[nt_][2], s3_ = (SF)[nt_][3]; \
        if (diag_) { \
            int cg_ = (T)*64 + nt_*8 + (lane & 3)*2; \
            if (cg_   > rg0)   s0_ = -1e30f; \
            if (cg_+1 > rg0)   s1_ = -1e30f; \
            if (cg_   > rg0+8) s2_ = -1e30f; \
            if (cg_+1 > rg0+8) s3_ = -1e30f; \
        } \
        (SF)[nt_][0] = s0_; (SF)[nt_][1] = s1_; (SF)[nt_][2] = s2_; (SF)[nt_][3] = s3_; \
        mx0_ = fmaxf(mx0_, fmaxf(s0_, s1_)); \
        mx1_ = fmaxf(mx1_, fmaxf(s2_, s3_)); \
    } \
    _Pragma("unroll") for (int o_ = 1; o_ <= 2; o_ <<= 1) { \
        mx0_ = fmaxf(mx0_, __shfl_xor_sync(0xffffffffu, mx0_, o_)); \
        mx1_ = fmaxf(mx1_, __shfl_xor_sync(0xffffffffu, mx1_, o_)); \
    } \
    const float mn0_ = fmaxf(m0, mx0_), mn1_ = fmaxf(m1, mx1_); \
    const float cr0_ = ex2f(m0 - mn0_), cr1_ = ex2f(m1 - mn1_); \
    uint32_t pa0_[8], pa1_[8]; \
    float la0_ = 0.f, la1_ = 0.f; \
    _Pragma("unroll") for (int nt_ = 0; nt_ < 8; nt_++) { \
        float p0_ = ex2f((SF)[nt_][0] - mn0_), p1_ = ex2f((SF)[nt_][1] - mn0_); \
        float p2_ = ex2f((SF)[nt_][2] - mn1_), p3_ = ex2f((SF)[nt_][3] - mn1_); \
        la0_ += p0_ + p1_; la1_ += p2_ + p3_; \
        __half2 h01_ = __floats2half2_rn(p0_, p1_); \
        __half2 h23_ = __floats2half2_rn(p2_, p3_); \
        pa0_[nt_] = *(uint32_t*)&h01_; \
        pa1_[nt_] = *(uint32_t*)&h23_; \
    } \
    _Pragma("unroll") for (int o_ = 1; o_ <= 2; o_ <<= 1) { \
        la0_ += __shfl_xor_sync(0xffffffffu, la0_, o_); \
        la1_ += __shfl_xor_sync(0xffffffffu, la1_, o_); \
    } \
    l0 = l0*cr0_ + la0_;  m0 = mn0_; \
    l1 = l1*cr1_ + la1_;  m1 = mn1_; \
    _Pragma("unroll") for (int t_ = 0; t_ < 16; t_++) { \
        of[t_][0] *= cr0_; of[t_][1] *= cr0_; \
        of[t_][2] *= cr1_; of[t_][3] *= cr1_; \
    } \
    _Pragma("unroll") for (int s_ = 0; s_ < 4; s_++) { \
        uint32_t pfr_[4] = {pa0_[2*s_], pa1_[2*s_], pa0_[2*s_+1], pa1_[2*s_+1]}; \
        _Pragma("unroll") for (int np_ = 0; np_ < 8; np_++) { \
            uint32_t w0_, w1_, w2_, w3_; \
            uint32_t ad_ = (VB) + (np_ >> 2)*8192 + \
                SWZ128((uint32_t)(s_*2048) + v_rsel + (np_ & 3)*32 + v_csel); \
            LDSM_X4T(w0_, w1_, w2_, w3_, ad_); \
            uint32_t vb0_[2] = {w0_, w1_}, vb1_[2] = {w2_, w3_}; \
            MMA16816(of[2*np_],   pfr_, vb0_); \
            MMA16816(of[2*np_+1], pfr_, vb1_); \
        } \
    } \
} while (0)

#define FA_BODY(JT, PROD, CONS, DO_CONS) do { \
    if ((JT) + 1 < nkv) FA_ISSUE((JT) + 1, stN); \
    CP_COMMIT(); \
    FA_SMM(PROD, stC); \
    if (DO_CONS) FA_SMPV(CONS, (JT) - 1, stP + 16384); \
    CP_WAIT0(); \
    __syncthreads(); \
} while (0)

    FA_BODY(0, sfA, sfB, false); FA_ROT();
    int jt = 1;
    for (; jt + 1 < nkv; jt += 2) {
        FA_BODY(jt,   sfB, sfA, true); FA_ROT();
        FA_BODY(jt+1, sfA, sfB, true); FA_ROT();
    }
    if (jt < nkv) {
        FA_BODY(jt, sfB, sfA, true); FA_ROT();
        FA_SMPV(sfB, nkv-1, stP + 16384);
    } else {
        FA_SMPV(sfA, nkv-1, stP + 16384);
    }

    const float il0 = 1.f / l0, il1 = 1.f / l1;
    __half* ob = out + (size_t)(qt*64 + wid*16 + (lane >> 2))*DMODEL + head*DHEAD + (lane & 3)*2;
    #pragma unroll
    for (int t = 0; t < 16; t++) {
        *(__half2*)(ob + t*8)            = __floats2half2_rn(of[t][0]*il0, of[t][1]*il0);
        *(__half2*)(ob + 8*DMODEL + t*8) = __floats2half2_rn(of[t][2]*il1, of[t][3]*il1);
    }
}

// ============================ launch ============================
extern "C" void kernel_launch(void* const* d_in, const int* in_sizes, int n_in,
                              void* d_out, int out_size)
{
    const float* x     = (const float*)d_in[0];
    const float* r_cos = (const float*)d_in[1];
    const float* r_sin = (const float*)d_in[2];
    /* d_in[3] mask: causal, implemented analytically */
    const float* nw    = (const float*)d_in[4];
    const float* wq    = (const float*)d_in[5];
    const float* wk    = (const float*)d_in[6];
    const float* wv    = (const float*)d_in[7];
    const float* wo    = (const float*)d_in[8];
    float* out = (float*)d_out;

    __half *h16, *wqkv16, *wo16, *qkv16, *attn16;
    cudaGetSymbolAddress((void**)&h16,    g_h16);
    cudaGetSymbolAddress((void**)&wqkv16, g_wqkv16);
    cudaGetSymbolAddress((void**)&wo16,   g_wo16);
    cudaGetSymbolAddress((void**)&qkv16,  g_qkv16);
    cudaGetSymbolAddress((void**)&attn16, g_attn16);

    cudaFuncSetAttribute(hgemm_mma<float>,  cudaFuncAttributeMaxDynamicSharedMemorySize, HG_SMEM);
    cudaFuncSetAttribute(hgemm_mma<__half>, cudaFuncAttributeMaxDynamicSharedMemorySize, HG_SMEM);
    cudaFuncSetAttribute(attn_mma,          cudaFuncAttributeMaxDynamicSharedMemorySize, FA_SMEM);

    // 1. fused prep: weight conversion + RMSNorm
    prep_kernel<<<NCVT + SQ, 256>>>((const float4*)wq, (const float4*)wk,
                                    (const float4*)wv, (const float4*)wo,
                                    (__half2*)wqkv16, (__half2*)wo16,
                                    x, nw, h16);

    // 2. fused QKV projection + RoPE + Q prescale (persistent HMMA, fp16 out)
    {
        int ntx = NQKV/128, ntiles = ntx * (SQ/128);
        int grid = ntiles < HG_GRID ? ntiles : HG_GRID;
        hgemm_mma<__half><<<grid, 256, HG_SMEM>>>(
            h16, wqkv16, qkv16, nullptr, SQ, NQKV, DMODEL, NQKV, ntx, ntiles, r_cos, r_sin);
    }

    // 3. causal GQA flash attention (HMMA, pipelined, 2 CTAs/SM)
    attn_mma<<<dim3(SQ/64, NHEADS), 128, FA_SMEM>>>(qkv16, attn16);

    // 4. output projection + residual (persistent HMMA, fp32 out)
    {
        int ntx = DMODEL/128, ntiles = ntx * (SQ/128);
        int grid = ntiles < HG_GRID ? ntiles : HG_GRID;
        hgemm_mma<float><<<grid, 256, HG_SMEM>>>(
            attn16, wo16, out, x, SQ, DMODEL, DMODEL, DMODEL, ntx, ntiles, nullptr, nullptr);
    }
}

// round 15
// speedup vs baseline: 1.0478x; 1.0478x over previous
#include <cuda_runtime.h>
#include <cuda_fp16.h>
#include <stdint.h>
#include <math.h>

#define SQ      2048
#define DMODEL  4096
#define DHEAD   128
#define NHEADS  32
#define NKV     8
#define KDIM_Q  (NHEADS*DHEAD)   /* 4096 */
#define KDIM_KV (NKV*DHEAD)      /* 1024 */
#define NQKV    (KDIM_Q + 2*KDIM_KV)  /* 6144 */
#define QS      (0.08838834764831845f * 1.44269504088896341f)  /* 1/sqrt(128) * log2(e) */

// -------- scratch (device globals: allocation-free) --------
__device__ __align__(256) __half g_h16[SQ*DMODEL];
__device__ __align__(256) __half g_wqkv16[NQKV*DMODEL];
__device__ __align__(256) __half g_wo16[DMODEL*DMODEL];
__device__ __align__(256) __half g_qkv16[SQ*NQKV];
__device__ __align__(256) __half g_attn16[SQ*DMODEL];

// ============================ helpers ============================
static __device__ __forceinline__ uint32_t smem_u32(const void* p) {
    uint32_t a;
    asm("{ .reg .u64 t; cvta.to.shared.u64 t, %1; cvt.u32.u64 %0, t; }" : "=r"(a) : "l"(p));
    return a;
}
static __device__ __forceinline__ float ex2f(float x) {
    float y; asm("ex2.approx.ftz.f32 %0, %1;" : "=f"(y) : "f"(x)); return y;
}
#define SWZ128(x) ((x) ^ (((x) >> 3) & 0x70))

#define CP16(s, g) \
    asm volatile("cp.async.cg.shared.global [%0], [%1], 16;" :: "r"(s), "l"(g) : "memory")
#define CP_COMMIT() asm volatile("cp.async.commit_group;" ::: "memory")
#define CP_WAIT0()  asm volatile("cp.async.wait_group 0;" ::: "memory")
#define CP_WAIT1()  asm volatile("cp.async.wait_group 1;" ::: "memory")

#define LDSM_X4(r0,r1,r2,r3,addr) \
    asm volatile("ldmatrix.sync.aligned.m8n8.x4.shared.b16 {%0,%1,%2,%3}, [%4];" \
        : "=r"(r0),"=r"(r1),"=r"(r2),"=r"(r3) : "r"(addr))
#define LDSM_X4T(r0,r1,r2,r3,addr) \
    asm volatile("ldmatrix.sync.aligned.m8n8.x4.trans.shared.b16 {%0,%1,%2,%3}, [%4];" \
        : "=r"(r0),"=r"(r1),"=r"(r2),"=r"(r3) : "r"(addr))

#define MMA16816(d, a, b) \
    asm volatile("mma.sync.aligned.m16n8k16.row.col.f32.f16.f16.f32 " \
        "{%0,%1,%2,%3}, {%4,%5,%6,%7}, {%8,%9}, {%0,%1,%2,%3};" \
        : "+f"((d)[0]),"+f"((d)[1]),"+f"((d)[2]),"+f"((d)[3]) \
        : "r"((a)[0]),"r"((a)[1]),"r"((a)[2]),"r"((a)[3]), "r"((b)[0]),"r"((b)[1]))

// ============================ fused prep: weight cvt + RMSNorm ============================
#define CVT_N4   ((KDIM_Q*DMODEL + 2*KDIM_KV*DMODEL + DMODEL*DMODEL) / 4)
#define NCVT     (CVT_N4 / 256)

__global__ __launch_bounds__(256) void prep_kernel(
    const float4* __restrict__ wq, const float4* __restrict__ wk,
    const float4* __restrict__ wv, const float4* __restrict__ wo,
    __half2* __restrict__ wqkv, __half2* __restrict__ wo16,
    const float* __restrict__ x, const float* __restrict__ nw, __half* __restrict__ h)
{
    if (blockIdx.x < NCVT) {
        int i = blockIdx.x * 256 + threadIdx.x;
        const int A = KDIM_Q*DMODEL/4;
        const int B = A + KDIM_KV*DMODEL/4;
        const int C = B + KDIM_KV*DMODEL/4;
        float4 v; __half2* o;
        if (i < A)      { v = wq[i];     o = wqkv + 2*(size_t)i; }
        else if (i < B) { v = wk[i-A];   o = wqkv + 2*(size_t)i; }
        else if (i < C) { v = wv[i-B];   o = wqkv + 2*(size_t)i; }
        else            { v = wo[i-C];   o = wo16 + 2*(size_t)(i-C); }
        o[0] = __floats2half2_rn(v.x, v.y);
        o[1] = __floats2half2_rn(v.z, v.w);
        return;
    }
    int row = blockIdx.x - NCVT;
    const float* xr = x + (size_t)row * DMODEL;
    float ss = 0.f;
    for (int i = threadIdx.x; i < DMODEL/4; i += blockDim.x) {
        float4 v = ((const float4*)xr)[i];
        ss += v.x*v.x + v.y*v.y + v.z*v.z + v.w*v.w;
    }
    __shared__ float red[32];
    #pragma unroll
    for (int o = 16; o > 0; o >>= 1) ss += __shfl_xor_sync(0xffffffffu, ss, o);
    if ((threadIdx.x & 31) == 0) red[threadIdx.x >> 5] = ss;
    __syncthreads();
    if (threadIdx.x < 32) {
        float v = (threadIdx.x < 8) ? red[threadIdx.x] : 0.f;
        #pragma unroll
        for (int o = 16; o > 0; o >>= 1) v += __shfl_xor_sync(0xffffffffu, v, o);
        if (threadIdx.x == 0) red[0] = v;
    }
    __syncthreads();
    float scale = rsqrtf(red[0] / (float)DMODEL + 1e-5f);
    __half2* hr = (__half2*)(h + (size_t)row * DMODEL);
    for (int i = threadIdx.x; i < DMODEL/4; i += blockDim.x) {
        float4 v  = ((const float4*)xr)[i];
        float4 wv = ((const float4*)nw)[i];
        hr[2*i+0] = __floats2half2_rn(v.x*scale*wv.x, v.y*scale*wv.y);
        hr[2*i+1] = __floats2half2_rn(v.z*scale*wv.z, v.w*scale*wv.w);
    }
}

// ============================ HMMA HGEMM (128x128, 3-stage, single sync, 2 CTA/SM) ============================
// Prefetch de-bursting: the 8 CP16s for stage i+2 are issued 2-per-ks-group inside
// the compute loop instead of front-batched (cuts L1tex queue burst / barrier skew).
#define HG_STAGE 32768
#define HG_SMEM  (3*HG_STAGE)

template<typename OutT>
__global__ __launch_bounds__(256, 2) void hgemm_mma(
    const __half* __restrict__ A, const __half* __restrict__ B,
    OutT* __restrict__ C, const float* __restrict__ R,
    int M, int N, int K, int ldC,
    const float* __restrict__ rc, const float* __restrict__ rs)
{
    extern __shared__ char sm[];
    const uint32_t sb = smem_u32(sm);
    const int tid  = threadIdx.x;
    const int lane = tid & 31;
    const int wid  = tid >> 5;
    const int wm   = wid & 1;
    const int wn   = wid >> 1;
    const int bm = blockIdx.y * 128;
    const int bn = blockIdx.x * 128;

    const __half* Agp = A + (size_t)bm * K;
    const __half* Bgp = B + (size_t)bn * K;

    const int lrow = tid >> 3;
    const int lch  = tid & 7;
    uint32_t swoff[4];
    #pragma unroll
    for (int j = 0; j < 4; j++)
        swoff[j] = SWZ128((uint32_t)((lrow + 32*j)*128 + lch*16));

    float acc[4][4][4];
    #pragma unroll
    for (int im = 0; im < 4; im++)
        #pragma unroll
        for (int in = 0; in < 4; in++)
            #pragma unroll
            for (int r = 0; r < 4; r++) acc[im][in][r] = 0.f;

    const int nk = K >> 6;

    // prologue: stages 0 and 1
    #pragma unroll
    for (int s = 0; s < 2; s++) {
        uint32_t ab = sb + s*HG_STAGE, bb = ab + 16384;
        const int k0 = s << 6;
        #pragma unroll
        for (int j = 0; j < 4; j++) {
            const size_t go = (size_t)(lrow + 32*j) * K + k0 + lch*8;
            CP16(ab + swoff[j], Agp + go);
            CP16(bb + swoff[j], Bgp + go);
        }
        CP_COMMIT();
    }

    const uint32_t a_row0 = (uint32_t)(wm*64 + (lane & 15)) * 128;
    const uint32_t a_csel = (uint32_t)(lane >> 4) * 16;
    const uint32_t b_row0 = (uint32_t)(wn*32 + ((lane >> 4) & 1)*8 + (lane & 7)) * 128;
    const uint32_t b_csel = (uint32_t)((lane >> 3) & 1) * 16;

    int sidx = 0;
    for (int i = 0; i < nk; i++) {
        CP_WAIT1();        // stage i complete (<=1 newer group pending)
        __syncthreads();   // cross-thread visibility; prev iter's readers done

        const bool pf = (i + 2 < nk);
        int tb = sidx + 2; if (tb >= 3) tb -= 3;
        const uint32_t ab = sb + tb*HG_STAGE, bb = ab + 16384;
        const int kpf = (i+2) << 6;

        const uint32_t As = sb + sidx*HG_STAGE;
        const uint32_t Bs = As + 16384;

        #pragma unroll
        for (int ks = 0; ks < 4; ks++) {
            // de-bursted prefetch: 2 CP16s per ks-group
            if (pf) {
                const size_t go = (size_t)(lrow + 32*ks) * K + kpf + lch*8;
                CP16(ab + swoff[ks], Agp + go);
                CP16(bb + swoff[ks], Bgp + go);
            }
            uint32_t af[4][4], bf[4][2];
            #pragma unroll
            for (int im = 0; im < 4; im++) {
                uint32_t off = SWZ128(a_row0 + (uint32_t)(im*2048) + ks*32 + a_csel);
                LDSM_X4(af[im][0], af[im][1], af[im][2], af[im][3], As + off);
            }
            #pragma unroll
            for (int ntp = 0; ntp < 2; ntp++) {
                uint32_t r0, r1, r2, r3;
                uint32_t off = SWZ128(b_row0 + (uint32_t)(ntp*16*128) + ks*32 + b_csel);
                LDSM_X4(r0, r1, r2, r3, Bs + off);
                bf[2*ntp][0] = r0;  bf[2*ntp][1] = r1;
                bf[2*ntp+1][0] = r2; bf[2*ntp+1][1] = r3;
            }
            #pragma unroll
            for (int im = 0; im < 4; im++)
                #pragma unroll
                for (int in = 0; in < 4; in++)
                    MMA16816(acc[im][in], af[im], bf[in]);
        }
        CP_COMMIT();       // exactly one group per iteration
        if (++sidx == 3) sidx = 0;
    }

    const bool dorope = (rc != nullptr) && (bn < KDIM_Q + KDIM_KV);
    const bool doq    = (bn < KDIM_Q);

    #pragma unroll
    for (int im = 0; im < 4; im++) {
        const int ro0 = bm + wm*64 + im*16 + (lane >> 2);
        const int ro1 = ro0 + 8;
        #pragma unroll
        for (int in = 0; in < 4; in++) {
            const int col = bn + wn*32 + in*8 + (lane & 3)*2;
            float a0 = acc[im][in][0], a1 = acc[im][in][1];
            float a2 = acc[im][in][2], a3 = acc[im][in][3];
            if (sizeof(OutT) == 2) {
                if (dorope) {
                    int dcol = col & 127;
                    float c0 = rc[(size_t)ro0*DHEAD + dcol], s0 = rs[(size_t)ro0*DHEAD + dcol];
                    float c1 = rc[(size_t)ro1*DHEAD + dcol], s1 = rs[(size_t)ro1*DHEAD + dcol];
                    float y0 = a0*c0 - a1*s0, y1 = a1*c0 + a0*s0;
                    float y2 = a2*c1 - a3*s1, y3 = a3*c1 + a2*s1;
                    if (doq) { y0 *= QS; y1 *= QS; y2 *= QS; y3 *= QS; }
                    a0 = y0; a1 = y1; a2 = y2; a3 = y3;
                }
                *(__half2*)((__half*)C + (size_t)ro0*ldC + col) = __floats2half2_rn(a0, a1);
                *(__half2*)((__half*)C + (size_t)ro1*ldC + col) = __floats2half2_rn(a2, a3);
            } else {
                float2 v0 = make_float2(a0, a1);
                float2 v1 = make_float2(a2, a3);
                if (R) {
                    const float2 q0 = *(const float2*)&R[(size_t)ro0*ldC + col];
                    const float2 q1 = *(const float2*)&R[(size_t)ro1*ldC + col];
                    v0.x += q0.x; v0.y += q0.y;
                    v1.x += q1.x; v1.y += q1.y;
                }
                *(float2*)((float*)C + (size_t)ro0*ldC + col) = v0;
                *(float2*)((float*)C + (size_t)ro1*ldC + col) = v1;
            }
        }
    }
}

// ============================ HMMA flash attention (causal GQA, pipelined, 2 CTA/SM) ============================
#define FA_Q    0
#define FA_KV   16384
#define FA_STG  32768
#define FA_SMEM (FA_KV + 3*FA_STG)   /* 112 KB */

__global__ __launch_bounds__(128) void attn_mma(
    const __half* __restrict__ qkv, __half* __restrict__ out)
{
    extern __shared__ char sm[];
    const uint32_t sb = smem_u32(sm);
    const int tid  = threadIdx.x;
    const int lane = tid & 31;
    const int wid  = tid >> 5;

    const int head = blockIdx.y;
    const int kvh  = head >> 2;
    const int qt   = gridDim.x - 1 - blockIdx.x;

    const int lch  = tid & 7;
    const int lr16 = tid >> 3;

    const __half* qg  = qkv + (size_t)(qt*64)*NQKV + head*DHEAD;
    const __half* kg0 = qkv + KDIM_Q + kvh*DHEAD;
    const __half* vg0 = qkv + KDIM_Q + KDIM_KV + kvh*DHEAD;

    const int nkv = qt + 1;

    uint32_t stP = sb + FA_KV + 2*FA_STG;
    uint32_t stC = sb + FA_KV + 0*FA_STG;
    uint32_t stN = sb + FA_KV + 1*FA_STG;
#define FA_ROT() do { uint32_t t_ = stP; stP = stC; stC = stN; stN = t_; } while (0)

#define FA_ISSUE(T, BASE) do { \
    const __half* kg_ = kg0 + (size_t)((T)*64)*NQKV; \
    const __half* vg_ = vg0 + (size_t)((T)*64)*NQKV; \
    _Pragma("unroll") for (int p_ = 0; p_ < 2; p_++) \
    _Pragma("unroll") for (int j_ = 0; j_ < 4; j_++) { \
        int row_ = j_*16 + lr16; \
        uint32_t so_ = SWZ128((uint32_t)(row_*128 + lch*16)); \
        CP16((BASE) + p_*8192 + so_,         kg_ + (size_t)row_*NQKV + p_*64 + lch*8); \
        CP16((BASE) + 16384 + p_*8192 + so_, vg_ + (size_t)row_*NQKV + p_*64 + lch*8); \
    } \
} while (0)

    #pragma unroll
    for (int p = 0; p < 2; p++)
        #pragma unroll
        for (int j = 0; j < 4; j++) {
            int row = j*16 + lr16;
            CP16(sb + FA_Q + p*8192 + SWZ128((uint32_t)(row*128 + lch*16)),
                 qg + (size_t)row*NQKV + p*64 + lch*8);
        }
    FA_ISSUE(0, stC);
    CP_COMMIT();
    CP_WAIT0();
    __syncthreads();

    uint32_t qf[8][4];
    {
        const uint32_t rowb = (uint32_t)(wid*16 + (lane & 15)) * 128;
        const uint32_t csel = (uint32_t)(lane >> 4) * 16;
        #pragma unroll
        for (int ks = 0; ks < 8; ks++) {
            uint32_t addr = sb + FA_Q + (ks >> 2)*8192 + SWZ128(rowb + (ks & 3)*32 + csel);
            LDSM_X4(qf[ks][0], qf[ks][1], qf[ks][2], qf[ks][3], addr);
        }
    }

    float of[16][4];
    #pragma unroll
    for (int t = 0; t < 16; t++)
        #pragma unroll
        for (int r = 0; r < 4; r++) of[t][r] = 0.f;
    float m0 = -1e30f, m1 = -1e30f, l0 = 0.f, l1 = 0.f;
    float sfA[8][4], sfB[8][4];

    const int rg0 = qt*64 + wid*16 + (lane >> 2);
    const uint32_t k_row0 = (uint32_t)(((lane >> 4) & 1)*8 + (lane & 7)) * 128;
    const uint32_t k_csel = (uint32_t)((lane >> 3) & 1) * 16;
    const uint32_t v_rsel = (uint32_t)(lane & 15) * 128;
    const uint32_t v_csel = (uint32_t)(lane >> 4) * 16;

#define FA_SMM(SF, KB) do { \
    _Pragma("unroll") for (int nt_ = 0; nt_ < 8; nt_++) \
        _Pragma("unroll") for (int r_ = 0; r_ < 4; r_++) (SF)[nt_][r_] = 0.f; \
    _Pragma("unroll") for (int ks_ = 0; ks_ < 8; ks_++) { \
        const uint32_t pb_ = (KB) + (ks_ >> 2)*8192; \
        const uint32_t co_ = (ks_ & 3)*32 + k_csel; \
        _Pragma("unroll") for (int ntp_ = 0; ntp_ < 4; ntp_++) { \
            uint32_t x0_, x1_, x2_, x3_; \
            LDSM_X4(x0_, x1_, x2_, x3_, pb_ + SWZ128(k_row0 + (uint32_t)(ntp_*2048) + co_)); \
            uint32_t bA_[2] = {x0_, x1_}, bB_[2] = {x2_, x3_}; \
            MMA16816((SF)[2*ntp_],   qf[ks_], bA_); \
            MMA16816((SF)[2*ntp_+1], qf[ks_], bB_); \
        } \
    } \
} while (0)

#define FA_SMPV(SF, T, VB) do { \
    const bool diag_ = (T) == qt; \
    float mx0_ = -1e30f, mx1_ = -1e30f; \
    _Pragma("unroll") for (int nt_ = 0; nt_ < 8; nt_++) { \
        float s0_ = (SF)[nt_][0], s1_ = (SF)[nt_][1]; \
        float s2_ = (SF)[nt_][2], s3_ = (SF)[nt_][3]; \
        if (diag_) { \
            int cg_ = (T)*64 + nt_*8 + (lane & 3)*2; \
            if (cg_   > rg0)   s0_ = -1e30f; \
            if (cg_+1 > rg0)   s1_ = -1e30f; \
            if (cg_   > rg0+8) s2_ = -1e30f; \
            if (cg_+1 > rg0+8) s3_ = -1e30f; \
        } \
        (SF)[nt_][0] = s0_; (SF)[nt_][1] = s1_; (SF)[nt_][2] = s2_; (SF)[nt_][3] = s3_; \
        mx0_ = fmaxf(mx0_, fmaxf(s0_, s1_)); \
        mx1_ = fmaxf(mx1_, fmaxf(s2_, s3_)); \
    } \
    _Pragma("unroll") for (int o_ = 1; o_ <= 2; o_ <<= 1) { \
        mx0_ = fmaxf(mx0_, __shfl_xor_sync(0xffffffffu, mx0_, o_)); \
        mx1_ = fmaxf(mx1_, __shfl_xor_sync(0xffffffffu, mx1_, o_)); \
    } \
    const float mn0_ = fmaxf(m0, mx0_), mn1_ = fmaxf(m1, mx1_); \
    const float cr0_ = ex2f(m0 - mn0_), cr1_ = ex2f(m1 - mn1_); \
    uint32_t pa0_[8], pa1_[8]; \
    float la0_ = 0.f, la1_ = 0.f; \
    _Pragma("unroll") for (int nt_ = 0; nt_ < 8; nt_++) { \
        float p0_ = ex2f((SF)[nt_][0] - mn0_), p1_ = ex2f((SF)[nt_][1] - mn0_); \
        float p2_ = ex2f((SF)[nt_][2] - mn1_), p3_ = ex2f((SF)[nt_][3] - mn1_); \
        la0_ += p0_ + p1_; la1_ += p2_ + p3_; \
        __half2 h01_ = __floats2half2_rn(p0_, p1_); \
        __half2 h23_ = __floats2half2_rn(p2_, p3_); \
        pa0_[nt_] = *(uint32_t*)&h01_; \
        pa1_[nt_] = *(uint32_t*)&h23_; \
    } \
    _Pragma("unroll") for (int o_ = 1; o_ <= 2; o_ <<= 1) { \
        la0_ += __shfl_xor_sync(0xffffffffu, la0_, o_); \
        la1_ += __shfl_xor_sync(0xffffffffu, la1_, o_); \
    } \
    l0 = l0*cr0_ + la0_;  m0 = mn0_; \
    l1 = l1*cr1_ + la1_;  m1 = mn1_; \
    _Pragma("unroll") for (int t_ = 0; t_ < 16; t_++) { \
        of[t_][0] *= cr0_; of[t_][1] *= cr0_; \
        of[t_][2] *= cr1_; of[t_][3] *= cr1_; \
    } \
    _Pragma("unroll") for (int s_ = 0; s_ < 4; s_++) { \
        uint32_t pfr_[4] = {pa0_[2*s_], pa1_[2*s_], pa0_[2*s_+1], pa1_[2*s_+1]}; \
        _Pragma("unroll") for (int np_ = 0; np_ < 8; np_++) { \
            uint32_t w0_, w1_, w2_, w3_; \
            uint32_t ad_ = (VB) + (np_ >> 2)*8192 + \
                SWZ128((uint32_t)(s_*2048) + v_rsel + (np_ & 3)*32 + v_csel); \
            LDSM_X4T(w0_, w1_, w2_, w3_, ad_); \
            uint32_t vb0_[2] = {w0_, w1_}, vb1_[2] = {w2_, w3_}; \
            MMA16816(of[2*np_],   pfr_, vb0_); \
            MMA16816(of[2*np_+1], pfr_, vb1_); \
        } \
    } \
} while (0)

#define FA_BODY(JT, PROD, CONS, DO_CONS) do { \
    if ((JT) + 1 < nkv) FA_ISSUE((JT) + 1, stN); \
    CP_COMMIT(); \
    FA_SMM(PROD, stC); \
    if (DO_CONS) FA_SMPV(CONS, (JT) - 1, stP + 16384); \
    CP_WAIT0(); \
    __syncthreads(); \
} while (0)

    FA_BODY(0, sfA, sfB, false); FA_ROT();
    int jt = 1;
    for (; jt + 1 < nkv; jt += 2) {
        FA_BODY(jt,   sfB, sfA, true); FA_ROT();
        FA_BODY(jt+1, sfA, sfB, true); FA_ROT();
    }
    if (jt < nkv) {
        FA_BODY(jt, sfB, sfA, true); FA_ROT();
        FA_SMPV(sfB, nkv-1, stP + 16384);
    } else {
        FA_SMPV(sfA, nkv-1, stP + 16384);
    }

    const float il0 = 1.f / l0, il1 = 1.f / l1;
    __half* ob = out + (size_t)(qt*64 + wid*16 + (lane >> 2))*DMODEL + head*DHEAD + (lane & 3)*2;
    #pragma unroll
    for (int t = 0; t < 16; t++) {
        *(__half2*)(ob + t*8)            = __floats2half2_rn(of[t][0]*il0, of[t][1]*il0);
        *(__half2*)(ob + 8*DMODEL + t*8) = __floats2half2_rn(of[t][2]*il1, of[t][3]*il1);
    }
}

// ============================ launch ============================
extern "C" void kernel_launch(void* const* d_in, const int* in_sizes, int n_in,
                              void* d_out, int out_size)
{
    const float* x     = (const float*)d_in[0];
    const float* r_cos = (const float*)d_in[1];
    const float* r_sin = (const float*)d_in[2];
    /* d_in[3] mask: causal, implemented analytically */
    const float* nw    = (const float*)d_in[4];
    const float* wq    = (const float*)d_in[5];
    const float* wk    = (const float*)d_in[6];
    const float* wv    = (const float*)d_in[7];
    const float* wo    = (const float*)d_in[8];
    float* out = (float*)d_out;

    __half *h16, *wqkv16, *wo16, *qkv16, *attn16;
    cudaGetSymbolAddress((void**)&h16,    g_h16);
    cudaGetSymbolAddress((void**)&wqkv16, g_wqkv16);
    cudaGetSymbolAddress((void**)&wo16,   g_wo16);
    cudaGetSymbolAddress((void**)&qkv16,  g_qkv16);
    cudaGetSymbolAddress((void**)&attn16, g_attn16);

    cudaFuncSetAttribute(hgemm_mma<float>,  cudaFuncAttributeMaxDynamicSharedMemorySize, HG_SMEM);
    cudaFuncSetAttribute(hgemm_mma<__half>, cudaFuncAttributeMaxDynamicSharedMemorySize, HG_SMEM);
    cudaFuncSetAttribute(attn_mma,          cudaFuncAttributeMaxDynamicSharedMemorySize, FA_SMEM);

    // 1. fused prep: weight conversion + RMSNorm
    prep_kernel<<<NCVT + SQ, 256>>>((const float4*)wq, (const float4*)wk,
                                    (const float4*)wv, (const float4*)wo,
                                    (__half2*)wqkv16, (__half2*)wo16,
                                    x, nw, h16);

    // 2. fused QKV projection + RoPE + Q prescale (HMMA, fp16 out)
    hgemm_mma<__half><<<dim3(NQKV/128, SQ/128), 256, HG_SMEM>>>(
        h16, wqkv16, qkv16, nullptr, SQ, NQKV, DMODEL, NQKV, r_cos, r_sin);

    // 3. causal GQA flash attention (HMMA, pipelined, 2 CTAs/SM)
    attn_mma<<<dim3(SQ/64, NHEADS), 128, FA_SMEM>>>(qkv16, attn16);

    // 4. output projection + residual (HMMA, fp32 out)
    hgemm_mma<float><<<dim3(DMODEL/128, SQ/128), 256, HG_SMEM>>>(
        attn16, wo16, out, x, SQ, DMODEL, DMODEL, DMODEL, nullptr, nullptr);
}

// round 16
// speedup vs baseline: 1.1011x; 1.0508x over previous
#include <cuda_runtime.h>
#include <cuda_fp16.h>
#include <stdint.h>
#include <math.h>

#define SQ      2048
#define DMODEL  4096
#define DHEAD   128
#define NHEADS  32
#define NKV     8
#define KDIM_Q  (NHEADS*DHEAD)   /* 4096 */
#define KDIM_KV (NKV*DHEAD)      /* 1024 */
#define NQKV    (KDIM_Q + 2*KDIM_KV)  /* 6144 */
#define QS      (0.08838834764831845f * 1.44269504088896341f)  /* 1/sqrt(128) * log2(e) */

// -------- scratch (device globals: allocation-free) --------
__device__ __align__(256) __half g_h16[SQ*DMODEL];
__device__ __align__(256) __half g_wqkv16[NQKV*DMODEL];
__device__ __align__(256) __half g_wo16[DMODEL*DMODEL];
__device__ __align__(256) __half g_qkv16[SQ*NQKV];
__device__ __align__(256) __half g_attn16[SQ*DMODEL];

// ============================ helpers ============================
static __device__ __forceinline__ uint32_t smem_u32(const void* p) {
    uint32_t a;
    asm("{ .reg .u64 t; cvta.to.shared.u64 t, %1; cvt.u32.u64 %0, t; }" : "=r"(a) : "l"(p));
    return a;
}
static __device__ __forceinline__ float ex2f(float x) {
    float y; asm("ex2.approx.ftz.f32 %0, %1;" : "=f"(y) : "f"(x)); return y;
}
#define SWZ128(x) ((x) ^ (((x) >> 3) & 0x70))

#define CP16(s, g) \
    asm volatile("cp.async.cg.shared.global [%0], [%1], 16;" :: "r"(s), "l"(g) : "memory")
#define CP_COMMIT() asm volatile("cp.async.commit_group;" ::: "memory")
#define CP_WAIT0()  asm volatile("cp.async.wait_group 0;" ::: "memory")
#define CP_WAIT1()  asm volatile("cp.async.wait_group 1;" ::: "memory")

#define LDSM_X4(r0,r1,r2,r3,addr) \
    asm volatile("ldmatrix.sync.aligned.m8n8.x4.shared.b16 {%0,%1,%2,%3}, [%4];" \
        : "=r"(r0),"=r"(r1),"=r"(r2),"=r"(r3) : "r"(addr))
#define LDSM_X4T(r0,r1,r2,r3,addr) \
    asm volatile("ldmatrix.sync.aligned.m8n8.x4.trans.shared.b16 {%0,%1,%2,%3}, [%4];" \
        : "=r"(r0),"=r"(r1),"=r"(r2),"=r"(r3) : "r"(addr))

#define MMA16816(d, a, b) \
    asm volatile("mma.sync.aligned.m16n8k16.row.col.f32.f16.f16.f32 " \
        "{%0,%1,%2,%3}, {%4,%5,%6,%7}, {%8,%9}, {%0,%1,%2,%3};" \
        : "+f"((d)[0]),"+f"((d)[1]),"+f"((d)[2]),"+f"((d)[3]) \
        : "r"((a)[0]),"r"((a)[1]),"r"((a)[2]),"r"((a)[3]), "r"((b)[0]),"r"((b)[1]))

// ============================ fused prep: weight cvt + RMSNorm ============================
#define CVT_N4   ((KDIM_Q*DMODEL + 2*KDIM_KV*DMODEL + DMODEL*DMODEL) / 4)
#define NCVT     (CVT_N4 / 256)

__global__ __launch_bounds__(256) void prep_kernel(
    const float4* __restrict__ wq, const float4* __restrict__ wk,
    const float4* __restrict__ wv, const float4* __restrict__ wo,
    __half2* __restrict__ wqkv, __half2* __restrict__ wo16,
    const float* __restrict__ x, const float* __restrict__ nw, __half* __restrict__ h)
{
    if (blockIdx.x < NCVT) {
        int i = blockIdx.x * 256 + threadIdx.x;
        const int A = KDIM_Q*DMODEL/4;
        const int B = A + KDIM_KV*DMODEL/4;
        const int C = B + KDIM_KV*DMODEL/4;
        float4 v; __half2* o;
        if (i < A)      { v = wq[i];     o = wqkv + 2*(size_t)i; }
        else if (i < B) { v = wk[i-A];   o = wqkv + 2*(size_t)i; }
        else if (i < C) { v = wv[i-B];   o = wqkv + 2*(size_t)i; }
        else            { v = wo[i-C];   o = wo16 + 2*(size_t)(i-C); }
        o[0] = __floats2half2_rn(v.x, v.y);
        o[1] = __floats2half2_rn(v.z, v.w);
        return;
    }
    int row = blockIdx.x - NCVT;
    const float* xr = x + (size_t)row * DMODEL;
    float ss = 0.f;
    for (int i = threadIdx.x; i < DMODEL/4; i += blockDim.x) {
        float4 v = ((const float4*)xr)[i];
        ss += v.x*v.x + v.y*v.y + v.z*v.z + v.w*v.w;
    }
    __shared__ float red[32];
    #pragma unroll
    for (int o = 16; o > 0; o >>= 1) ss += __shfl_xor_sync(0xffffffffu, ss, o);
    if ((threadIdx.x & 31) == 0) red[threadIdx.x >> 5] = ss;
    __syncthreads();
    if (threadIdx.x < 32) {
        float v = (threadIdx.x < 8) ? red[threadIdx.x] : 0.f;
        #pragma unroll
        for (int o = 16; o > 0; o >>= 1) v += __shfl_xor_sync(0xffffffffu, v, o);
        if (threadIdx.x == 0) red[0] = v;
    }
    __syncthreads();
    float scale = rsqrtf(red[0] / (float)DMODEL + 1e-5f);
    __half2* hr = (__half2*)(h + (size_t)row * DMODEL);
    for (int i = threadIdx.x; i < DMODEL/4; i += blockDim.x) {
        float4 v  = ((const float4*)xr)[i];
        float4 wv = ((const float4*)nw)[i];
        hr[2*i+0] = __floats2half2_rn(v.x*scale*wv.x, v.y*scale*wv.y);
        hr[2*i+1] = __floats2half2_rn(v.z*scale*wv.z, v.w*scale*wv.w);
    }
}

// ============================ HMMA HGEMM (r13 champion: 128x128, 3-stage, 2 CTA/SM) ============================
#define HG_STAGE 32768
#define HG_SMEM  (3*HG_STAGE)

template<typename OutT>
__global__ __launch_bounds__(256, 2) void hgemm_mma(
    const __half* __restrict__ A, const __half* __restrict__ B,
    OutT* __restrict__ C, const float* __restrict__ R,
    int M, int N, int K, int ldC,
    const float* __restrict__ rc, const float* __restrict__ rs)
{
    extern __shared__ char sm[];
    const uint32_t sb = smem_u32(sm);
    const int tid  = threadIdx.x;
    const int lane = tid & 31;
    const int wid  = tid >> 5;
    const int wm   = wid & 1;
    const int wn   = wid >> 1;
    const int bm = blockIdx.y * 128;
    const int bn = blockIdx.x * 128;

    const __half* Agp = A + (size_t)bm * K;
    const __half* Bgp = B + (size_t)bn * K;

    const int lrow = tid >> 3;
    const int lch  = tid & 7;
    uint32_t swoff[4];
    #pragma unroll
    for (int j = 0; j < 4; j++)
        swoff[j] = SWZ128((uint32_t)((lrow + 32*j)*128 + lch*16));

    float acc[4][4][4];
    #pragma unroll
    for (int im = 0; im < 4; im++)
        #pragma unroll
        for (int in = 0; in < 4; in++)
            #pragma unroll
            for (int r = 0; r < 4; r++) acc[im][in][r] = 0.f;

    const int nk = K >> 6;

    #pragma unroll
    for (int s = 0; s < 2; s++) {
        uint32_t ab = sb + s*HG_STAGE, bb = ab + 16384;
        const int k0 = s << 6;
        #pragma unroll
        for (int j = 0; j < 4; j++) {
            const size_t go = (size_t)(lrow + 32*j) * K + k0 + lch*8;
            CP16(ab + swoff[j], Agp + go);
            CP16(bb + swoff[j], Bgp + go);
        }
        CP_COMMIT();
    }

    const uint32_t a_row0 = (uint32_t)(wm*64 + (lane & 15)) * 128;
    const uint32_t a_csel = (uint32_t)(lane >> 4) * 16;
    const uint32_t b_row0 = (uint32_t)(wn*32 + ((lane >> 4) & 1)*8 + (lane & 7)) * 128;
    const uint32_t b_csel = (uint32_t)((lane >> 3) & 1) * 16;

    int sidx = 0;
    for (int i = 0; i < nk; i++) {
        CP_WAIT1();
        __syncthreads();

        if (i + 2 < nk) {
            int tb = sidx + 2; if (tb >= 3) tb -= 3;
            uint32_t ab = sb + tb*HG_STAGE, bb = ab + 16384;
            const int k0 = (i+2) << 6;
            #pragma unroll
            for (int j = 0; j < 4; j++) {
                const size_t go = (size_t)(lrow + 32*j) * K + k0 + lch*8;
                CP16(ab + swoff[j], Agp + go);
                CP16(bb + swoff[j], Bgp + go);
            }
        }
        CP_COMMIT();

        const uint32_t As = sb + sidx*HG_STAGE;
        const uint32_t Bs = As + 16384;

        #pragma unroll
        for (int ks = 0; ks < 4; ks++) {
            uint32_t af[4][4], bf[4][2];
            #pragma unroll
            for (int im = 0; im < 4; im++) {
                uint32_t off = SWZ128(a_row0 + (uint32_t)(im*2048) + ks*32 + a_csel);
                LDSM_X4(af[im][0], af[im][1], af[im][2], af[im][3], As + off);
            }
            #pragma unroll
            for (int ntp = 0; ntp < 2; ntp++) {
                uint32_t r0, r1, r2, r3;
                uint32_t off = SWZ128(b_row0 + (uint32_t)(ntp*16*128) + ks*32 + b_csel);
                LDSM_X4(r0, r1, r2, r3, Bs + off);
                bf[2*ntp][0] = r0;  bf[2*ntp][1] = r1;
                bf[2*ntp+1][0] = r2; bf[2*ntp+1][1] = r3;
            }
            #pragma unroll
            for (int im = 0; im < 4; im++)
                #pragma unroll
                for (int in = 0; in < 4; in++)
                    MMA16816(acc[im][in], af[im], bf[in]);
        }
        if (++sidx == 3) sidx = 0;
    }

    const bool dorope = (rc != nullptr) && (bn < KDIM_Q + KDIM_KV);
    const bool doq    = (bn < KDIM_Q);

    #pragma unroll
    for (int im = 0; im < 4; im++) {
        const int ro0 = bm + wm*64 + im*16 + (lane >> 2);
        const int ro1 = ro0 + 8;
        #pragma unroll
        for (int in = 0; in < 4; in++) {
            const int col = bn + wn*32 + in*8 + (lane & 3)*2;
            float a0 = acc[im][in][0], a1 = acc[im][in][1];
            float a2 = acc[im][in][2], a3 = acc[im][in][3];
            if (sizeof(OutT) == 2) {
                if (dorope) {
                    int dcol = col & 127;
                    float c0 = rc[(size_t)ro0*DHEAD + dcol], s0 = rs[(size_t)ro0*DHEAD + dcol];
                    float c1 = rc[(size_t)ro1*DHEAD + dcol], s1 = rs[(size_t)ro1*DHEAD + dcol];
                    float y0 = a0*c0 - a1*s0, y1 = a1*c0 + a0*s0;
                    float y2 = a2*c1 - a3*s1, y3 = a3*c1 + a2*s1;
                    if (doq) { y0 *= QS; y1 *= QS; y2 *= QS; y3 *= QS; }
                    a0 = y0; a1 = y1; a2 = y2; a3 = y3;
                }
                *(__half2*)((__half*)C + (size_t)ro0*ldC + col) = __floats2half2_rn(a0, a1);
                *(__half2*)((__half*)C + (size_t)ro1*ldC + col) = __floats2half2_rn(a2, a3);
            } else {
                float2 v0 = make_float2(a0, a1);
                float2 v1 = make_float2(a2, a3);
                if (R) {
                    const float2 q0 = *(const float2*)&R[(size_t)ro0*ldC + col];
                    const float2 q1 = *(const float2*)&R[(size_t)ro1*ldC + col];
                    v0.x += q0.x; v0.y += q0.y;
                    v1.x += q1.x; v1.y += q1.y;
                }
                *(float2*)((float*)C + (size_t)ro0*ldC + col) = v0;
                *(float2*)((float*)C + (size_t)ro1*ldC + col) = v1;
            }
        }
    }
}

// ============================ HMMA flash attention (causal GQA, pipelined, 2 CTA/SM) ============================
#define FA_Q    0
#define FA_KV   16384
#define FA_STG  32768
#define FA_SMEM (FA_KV + 3*FA_STG)   /* 112 KB */

__global__ __launch_bounds__(128) void attn_mma(
    const __half* __restrict__ qkv, __half* __restrict__ out)
{
    extern __shared__ char sm[];
    const uint32_t sb = smem_u32(sm);
    const int tid  = threadIdx.x;
    const int lane = tid & 31;
    const int wid  = tid >> 5;

    const int head = blockIdx.y;
    const int kvh  = head >> 2;
    const int qt   = gridDim.x - 1 - blockIdx.x;

    const int lch  = tid & 7;
    const int lr16 = tid >> 3;

    const __half* qg  = qkv + (size_t)(qt*64)*NQKV + head*DHEAD;
    const __half* kg0 = qkv + KDIM_Q + kvh*DHEAD;
    const __half* vg0 = qkv + KDIM_Q + KDIM_KV + kvh*DHEAD;

    const int nkv = qt + 1;

    uint32_t stP = sb + FA_KV + 2*FA_STG;
    uint32_t stC = sb + FA_KV + 0*FA_STG;
    uint32_t stN = sb + FA_KV + 1*FA_STG;
#define FA_ROT() do { uint32_t t_ = stP; stP = stC; stC = stN; stN = t_; } while (0)

#define FA_ISSUE(T, BASE) do { \
    const __half* kg_ = kg0 + (size_t)((T)*64)*NQKV; \
    const __half* vg_ = vg0 + (size_t)((T)*64)*NQKV; \
    _Pragma("unroll") for (int p_ = 0; p_ < 2; p_++) \
    _Pragma("unroll") for (int j_ = 0; j_ < 4; j_++) { \
        int row_ = j_*16 + lr16; \
        uint32_t so_ = SWZ128((uint32_t)(row_*128 + lch*16)); \
        CP16((BASE) + p_*8192 + so_,         kg_ + (size_t)row_*NQKV + p_*64 + lch*8); \
        CP16((BASE) + 16384 + p_*8192 + so_, vg_ + (size_t)row_*NQKV + p_*64 + lch*8); \
    } \
} while (0)

    #pragma unroll
    for (int p = 0; p < 2; p++)
        #pragma unroll
        for (int j = 0; j < 4; j++) {
            int row = j*16 + lr16;
            CP16(sb + FA_Q + p*8192 + SWZ128((uint32_t)(row*128 + lch*16)),
                 qg + (size_t)row*NQKV + p*64 + lch*8);
        }
    FA_ISSUE(0, stC);
    CP_COMMIT();
    CP_WAIT0();
    __syncthreads();

    uint32_t qf[8][4];
    {
        const uint32_t rowb = (uint32_t)(wid*16 + (lane & 15)) * 128;
        const uint32_t csel = (uint32_t)(lane >> 4) * 16;
        #pragma unroll
        for (int ks = 0; ks < 8; ks++) {
            uint32_t addr = sb + FA_Q + (ks >> 2)*8192 + SWZ128(rowb + (ks & 3)*32 + csel);
            LDSM_X4(qf[ks][0], qf[ks][1], qf[ks][2], qf[ks][3], addr);
        }
    }

    float of[16][4];
    #pragma unroll
    for (int t = 0; t < 16; t++)
        #pragma unroll
        for (int r = 0; r < 4; r++) of[t][r] = 0.f;
    float m0 = -1e30f, m1 = -1e30f, l0 = 0.f, l1 = 0.f;
    float sfA[8][4], sfB[8][4];

    const int rg0 = qt*64 + wid*16 + (lane >> 2);
    const uint32_t k_row0 = (uint32_t)(((lane >> 4) & 1)*8 + (lane & 7)) * 128;
    const uint32_t k_csel = (uint32_t)((lane >> 3) & 1) * 16;
    const uint32_t v_rsel = (uint32_t)(lane & 15) * 128;
    const uint32_t v_csel = (uint32_t)(lane >> 4) * 16;

#define FA_SMM(SF, KB) do { \
    _Pragma("unroll") for (int nt_ = 0; nt_ < 8; nt_++) \
        _Pragma("unroll") for (int r_ = 0; r_ < 4; r_++) (SF)[nt_][r_] = 0.f; \
    _Pragma("unroll") for (int ks_ = 0; ks_ < 8; ks_++) { \
        const uint32_t pb_ = (KB) + (ks_ >> 2)*8192; \
        const uint32_t co_ = (ks_ & 3)*32 + k_csel; \
        _Pragma("unroll") for (int ntp_ = 0; ntp_ < 4; ntp_++) { \
            uint32_t x0_, x1_, x2_, x3_; \
            LDSM_X4(x0_, x1_, x2_, x3_, pb_ + SWZ128(k_row0 + (uint32_t)(ntp_*2048) + co_)); \
            uint32_t bA_[2] = {x0_, x1_}, bB_[2] = {x2_, x3_}; \
            MMA16816((SF)[2*ntp_],   qf[ks_], bA_); \
            MMA16816((SF)[2*ntp_+1], qf[ks_], bB_); \
        } \
    } \
} while (0)

#define FA_SMPV(SF, T, VB) do { \
    const bool diag_ = (T) == qt; \
    float mx0_ = -1e30f, mx1_ = -1e30f; \
    _Pragma("unroll") for (int nt_ = 0; nt_ < 8; nt_++) { \
        float s0_ = (SF)[nt_][0], s1_ = (SF)[nt_][1]; \
        float s2_ = (SF)[nt_][2], s3_ = (SF)[nt_][3]; \
        if (diag_) { \
            int cg_ = (T)*64 + nt_*8 + (lane & 3)*2; \
            if (cg_   > rg0)   s0_ = -1e30f; \
            if (cg_+1 > rg0)   s1_ = -1e30f; \
            if (cg_   > rg0+8) s2_ = -1e30f; \
            if (cg_+1 > rg0+8) s3_ = -1e30f; \
        } \
        (SF)[nt_][0] = s0_; (SF)[nt_][1] = s1_; (SF)[nt_][2] = s2_; (SF)[nt_][3] = s3_; \
        mx0_ = fmaxf(mx0_, fmaxf(s0_, s1_)); \
        mx1_ = fmaxf(mx1_, fmaxf(s2_, s3_)); \
    } \
    _Pragma("unroll") for (int o_ = 1; o_ <= 2; o_ <<= 1) { \
        mx0_ = fmaxf(mx0_, __shfl_xor_sync(0xffffffffu, mx0_, o_)); \
        mx1_ = fmaxf(mx1_, __shfl_xor_sync(0xffffffffu, mx1_, o_)); \
    } \
    const float mn0_ = fmaxf(m0, mx0_), mn1_ = fmaxf(m1, mx1_); \
    const float cr0_ = ex2f(m0 - mn0_), cr1_ = ex2f(m1 - mn1_); \
    uint32_t pa0_[8], pa1_[8]; \
    float la0_ = 0.f, la1_ = 0.f; \
    _Pragma("unroll") for (int nt_ = 0; nt_ < 8; nt_++) { \
        float p0_ = ex2f((SF)[nt_][0] - mn0_), p1_ = ex2f((SF)[nt_][1] - mn0_); \
        float p2_ = ex2f((SF)[nt_][2] - mn1_), p3_ = ex2f((SF)[nt_][3] - mn1_); \
        la0_ += p0_ + p1_; la1_ += p2_ + p3_; \
        __half2 h01_ = __floats2half2_rn(p0_, p1_); \
        __half2 h23_ = __floats2half2_rn(p2_, p3_); \
        pa0_[nt_] = *(uint32_t*)&h01_; \
        pa1_[nt_] = *(uint32_t*)&h23_; \
    } \
    _Pragma("unroll") for (int o_ = 1; o_ <= 2; o_ <<= 1) { \
        la0_ += __shfl_xor_sync(0xffffffffu, la0_, o_); \
        la1_ += __shfl_xor_sync(0xffffffffu, la1_, o_); \
    } \
    l0 = l0*cr0_ + la0_;  m0 = mn0_; \
    l1 = l1*cr1_ + la1_;  m1 = mn1_; \
    _Pragma("unroll") for (int t_ = 0; t_ < 16; t_++) { \
        of[t_][0] *= cr0_; of[t_][1] *= cr0_; \
        of[t_][2] *= cr1_; of[t_][3] *= cr1_; \
    } \
    _Pragma("unroll") for (int s_ = 0; s_ < 4; s_++) { \
        uint32_t pfr_[4] = {pa0_[2*s_], pa1_[2*s_], pa0_[2*s_+1], pa1_[2*s_+1]}; \
        _Pragma("unroll") for (int np_ = 0; np_ < 8; np_++) { \
            uint32_t w0_, w1_, w2_, w3_; \
            uint32_t ad_ = (VB) + (np_ >> 2)*8192 + \
                SWZ128((uint32_t)(s_*2048) + v_rsel + (np_ & 3)*32 + v_csel); \
            LDSM_X4T(w0_, w1_, w2_, w3_, ad_); \
            uint32_t vb0_[2] = {w0_, w1_}, vb1_[2] = {w2_, w3_}; \
            MMA16816(of[2*np_],   pfr_, vb0_); \
            MMA16816(of[2*np_+1], pfr_, vb1_); \
        } \
    } \
} while (0)

#define FA_BODY(JT, PROD, CONS, DO_CONS) do { \
    if ((JT) + 1 < nkv) FA_ISSUE((JT) + 1, stN); \
    CP_COMMIT(); \
    FA_SMM(PROD, stC); \
    if (DO_CONS) FA_SMPV(CONS, (JT) - 1, stP + 16384); \
    CP_WAIT0(); \
    __syncthreads(); \
} while (0)

    FA_BODY(0, sfA, sfB, false); FA_ROT();
    int jt = 1;
    for (; jt + 1 < nkv; jt += 2) {
        FA_BODY(jt,   sfB, sfA, true); FA_ROT();
        FA_BODY(jt+1, sfA, sfB, true); FA_ROT();
    }
    if (jt < nkv) {
        FA_BODY(jt, sfB, sfA, true); FA_ROT();
        FA_SMPV(sfB, nkv-1, stP + 16384);
    } else {
        FA_SMPV(sfA, nkv-1, stP + 16384);
    }

    const float il0 = 1.f / l0, il1 = 1.f / l1;
    __half* ob = out + (size_t)(qt*64 + wid*16 + (lane >> 2))*DMODEL + head*DHEAD + (lane & 3)*2;
    #pragma unroll
    for (int t = 0; t < 16; t++) {
        *(__half2*)(ob + t*8)            = __floats2half2_rn(of[t][0]*il0, of[t][1]*il0);
        *(__half2*)(ob + 8*DMODEL + t*8) = __floats2half2_rn(of[t][2]*il1, of[t][3]*il1);
    }
}

// ============================ launch ============================
extern "C" void kernel_launch(void* const* d_in, const int* in_sizes, int n_in,
                              void* d_out, int out_size)
{
    const float* x     = (const float*)d_in[0];
    const float* r_cos = (const float*)d_in[1];
    const float* r_sin = (const float*)d_in[2];
    /* d_in[3] mask: causal, implemented analytically */
    const float* nw    = (const float*)d_in[4];
    const float* wq    = (const float*)d_in[5];
    const float* wk    = (const float*)d_in[6];
    const float* wv    = (const float*)d_in[7];
    const float* wo    = (const float*)d_in[8];
    float* out = (float*)d_out;

    __half *h16, *wqkv16, *wo16, *qkv16, *attn16;
    cudaGetSymbolAddress((void**)&h16,    g_h16);
    cudaGetSymbolAddress((void**)&wqkv16, g_wqkv16);
    cudaGetSymbolAddress((void**)&wo16,   g_wo16);
    cudaGetSymbolAddress((void**)&qkv16,  g_qkv16);
    cudaGetSymbolAddress((void**)&attn16, g_attn16);

    cudaFuncSetAttribute(hgemm_mma<float>,  cudaFuncAttributeMaxDynamicSharedMemorySize, HG_SMEM);
    cudaFuncSetAttribute(hgemm_mma<__half>, cudaFuncAttributeMaxDynamicSharedMemorySize, HG_SMEM);
    cudaFuncSetAttribute(attn_mma,          cudaFuncAttributeMaxDynamicSharedMemorySize, FA_SMEM);

    // 1. fused prep: weight conversion + RMSNorm
    prep_kernel<<<NCVT + SQ, 256>>>((const float4*)wq, (const float4*)wk,
                                    (const float4*)wv, (const float4*)wo,
                                    (__half2*)wqkv16, (__half2*)wo16,
                                    x, nw, h16);

    // 2. fused QKV projection + RoPE + Q prescale (HMMA, fp16 out)
    hgemm_mma<__half><<<dim3(NQKV/128, SQ/128), 256, HG_SMEM>>>(
        h16, wqkv16, qkv16, nullptr, SQ, NQKV, DMODEL, NQKV, r_cos, r_sin);

    // 3. causal GQA flash attention (HMMA, pipelined, 2 CTAs/SM)
    attn_mma<<<dim3(SQ/64, NHEADS), 128, FA_SMEM>>>(qkv16, attn16);

    // 4. output projection + residual (HMMA, fp32 out)
    hgemm_mma<float><<<dim3(DMODEL/128, SQ/128), 256, HG_SMEM>>>(
        attn16, wo16, out, x, SQ, DMODEL, DMODEL, DMODEL, nullptr, nullptr);
}

// round 17
// speedup vs baseline: 1.1459x; 1.0407x over previous
#include <cuda_runtime.h>
#include <cuda_fp16.h>
#include <stdint.h>
#include <math.h>

#define SQ      2048
#define DMODEL  4096
#define DHEAD   128
#define NHEADS  32
#define NKV     8
#define KDIM_Q  (NHEADS*DHEAD)   /* 4096 */
#define KDIM_KV (NKV*DHEAD)      /* 1024 */
#define NQKV    (KDIM_Q + 2*KDIM_KV)  /* 6144 */
#define QS      (0.08838834764831845f * 1.44269504088896341f)  /* 1/sqrt(128) * log2(e) */
#define NQT     (SQ/64)          /* 32 q-tiles */

// -------- scratch (device globals: allocation-free) --------
__device__ __align__(256) __half g_h16[SQ*DMODEL];
__device__ __align__(256) __half g_wqkv16[NQKV*DMODEL];
__device__ __align__(256) __half g_wo16[DMODEL*DMODEL];
__device__ __align__(256) __half g_qkv16[SQ*NQKV];
__device__ __align__(256) __half g_attn16[SQ*DMODEL];

// ============================ helpers ============================
static __device__ __forceinline__ uint32_t smem_u32(const void* p) {
    uint32_t a;
    asm("{ .reg .u64 t; cvta.to.shared.u64 t, %1; cvt.u32.u64 %0, t; }" : "=r"(a) : "l"(p));
    return a;
}
static __device__ __forceinline__ float ex2f(float x) {
    float y; asm("ex2.approx.ftz.f32 %0, %1;" : "=f"(y) : "f"(x)); return y;
}
#define SWZ128(x) ((x) ^ (((x) >> 3) & 0x70))

#define CP16(s, g) \
    asm volatile("cp.async.cg.shared.global [%0], [%1], 16;" :: "r"(s), "l"(g) : "memory")
#define CP_COMMIT() asm volatile("cp.async.commit_group;" ::: "memory")
#define CP_WAIT0()  asm volatile("cp.async.wait_group 0;" ::: "memory")
#define CP_WAIT1()  asm volatile("cp.async.wait_group 1;" ::: "memory")

#define LDSM_X4(r0,r1,r2,r3,addr) \
    asm volatile("ldmatrix.sync.aligned.m8n8.x4.shared.b16 {%0,%1,%2,%3}, [%4];" \
        : "=r"(r0),"=r"(r1),"=r"(r2),"=r"(r3) : "r"(addr))
#define LDSM_X4T(r0,r1,r2,r3,addr) \
    asm volatile("ldmatrix.sync.aligned.m8n8.x4.trans.shared.b16 {%0,%1,%2,%3}, [%4];" \
        : "=r"(r0),"=r"(r1),"=r"(r2),"=r"(r3) : "r"(addr))

#define MMA16816(d, a, b) \
    asm volatile("mma.sync.aligned.m16n8k16.row.col.f32.f16.f16.f32 " \
        "{%0,%1,%2,%3}, {%4,%5,%6,%7}, {%8,%9}, {%0,%1,%2,%3};" \
        : "+f"((d)[0]),"+f"((d)[1]),"+f"((d)[2]),"+f"((d)[3]) \
        : "r"((a)[0]),"r"((a)[1]),"r"((a)[2]),"r"((a)[3]), "r"((b)[0]),"r"((b)[1]))

// ============================ fused prep: weight cvt + RMSNorm ============================
#define CVT_N4   ((KDIM_Q*DMODEL + 2*KDIM_KV*DMODEL + DMODEL*DMODEL) / 4)
#define NCVT     (CVT_N4 / 256)

__global__ __launch_bounds__(256) void prep_kernel(
    const float4* __restrict__ wq, const float4* __restrict__ wk,
    const float4* __restrict__ wv, const float4* __restrict__ wo,
    __half2* __restrict__ wqkv, __half2* __restrict__ wo16,
    const float* __restrict__ x, const float* __restrict__ nw, __half* __restrict__ h)
{
    if (blockIdx.x < NCVT) {
        int i = blockIdx.x * 256 + threadIdx.x;
        const int A = KDIM_Q*DMODEL/4;
        const int B = A + KDIM_KV*DMODEL/4;
        const int C = B + KDIM_KV*DMODEL/4;
        float4 v; __half2* o;
        if (i < A)      { v = wq[i];     o = wqkv + 2*(size_t)i; }
        else if (i < B) { v = wk[i-A];   o = wqkv + 2*(size_t)i; }
        else if (i < C) { v = wv[i-B];   o = wqkv + 2*(size_t)i; }
        else            { v = wo[i-C];   o = wo16 + 2*(size_t)(i-C); }
        o[0] = __floats2half2_rn(v.x, v.y);
        o[1] = __floats2half2_rn(v.z, v.w);
        return;
    }
    int row = blockIdx.x - NCVT;
    const float* xr = x + (size_t)row * DMODEL;
    float ss = 0.f;
    for (int i = threadIdx.x; i < DMODEL/4; i += blockDim.x) {
        float4 v = ((const float4*)xr)[i];
        ss += v.x*v.x + v.y*v.y + v.z*v.z + v.w*v.w;
    }
    __shared__ float red[32];
    #pragma unroll
    for (int o = 16; o > 0; o >>= 1) ss += __shfl_xor_sync(0xffffffffu, ss, o);
    if ((threadIdx.x & 31) == 0) red[threadIdx.x >> 5] = ss;
    __syncthreads();
    if (threadIdx.x < 32) {
        float v = (threadIdx.x < 8) ? red[threadIdx.x] : 0.f;
        #pragma unroll
        for (int o = 16; o > 0; o >>= 1) v += __shfl_xor_sync(0xffffffffu, v, o);
        if (threadIdx.x == 0) red[0] = v;
    }
    __syncthreads();
    float scale = rsqrtf(red[0] / (float)DMODEL + 1e-5f);
    __half2* hr = (__half2*)(h + (size_t)row * DMODEL);
    for (int i = threadIdx.x; i < DMODEL/4; i += blockDim.x) {
        float4 v  = ((const float4*)xr)[i];
        float4 wv = ((const float4*)nw)[i];
        hr[2*i+0] = __floats2half2_rn(v.x*scale*wv.x, v.y*scale*wv.y);
        hr[2*i+1] = __floats2half2_rn(v.z*scale*wv.z, v.w*scale*wv.w);
    }
}

// ============================ HMMA HGEMM (champion: 128x128, 3-stage, 2 CTA/SM) ============================
#define HG_STAGE 32768
#define HG_SMEM  (3*HG_STAGE)

template<typename OutT>
__global__ __launch_bounds__(256, 2) void hgemm_mma(
    const __half* __restrict__ A, const __half* __restrict__ B,
    OutT* __restrict__ C, const float* __restrict__ R,
    int M, int N, int K, int ldC,
    const float* __restrict__ rc, const float* __restrict__ rs)
{
    extern __shared__ char sm[];
    const uint32_t sb = smem_u32(sm);
    const int tid  = threadIdx.x;
    const int lane = tid & 31;
    const int wid  = tid >> 5;
    const int wm   = wid & 1;
    const int wn   = wid >> 1;
    const int bm = blockIdx.y * 128;
    const int bn = blockIdx.x * 128;

    const __half* Agp = A + (size_t)bm * K;
    const __half* Bgp = B + (size_t)bn * K;

    const int lrow = tid >> 3;
    const int lch  = tid & 7;
    uint32_t swoff[4];
    #pragma unroll
    for (int j = 0; j < 4; j++)
        swoff[j] = SWZ128((uint32_t)((lrow + 32*j)*128 + lch*16));

    float acc[4][4][4];
    #pragma unroll
    for (int im = 0; im < 4; im++)
        #pragma unroll
        for (int in = 0; in < 4; in++)
            #pragma unroll
            for (int r = 0; r < 4; r++) acc[im][in][r] = 0.f;

    const int nk = K >> 6;

    #pragma unroll
    for (int s = 0; s < 2; s++) {
        uint32_t ab = sb + s*HG_STAGE, bb = ab + 16384;
        const int k0 = s << 6;
        #pragma unroll
        for (int j = 0; j < 4; j++) {
            const size_t go = (size_t)(lrow + 32*j) * K + k0 + lch*8;
            CP16(ab + swoff[j], Agp + go);
            CP16(bb + swoff[j], Bgp + go);
        }
        CP_COMMIT();
    }

    const uint32_t a_row0 = (uint32_t)(wm*64 + (lane & 15)) * 128;
    const uint32_t a_csel = (uint32_t)(lane >> 4) * 16;
    const uint32_t b_row0 = (uint32_t)(wn*32 + ((lane >> 4) & 1)*8 + (lane & 7)) * 128;
    const uint32_t b_csel = (uint32_t)((lane >> 3) & 1) * 16;

    int sidx = 0;
    for (int i = 0; i < nk; i++) {
        CP_WAIT1();
        __syncthreads();

        if (i + 2 < nk) {
            int tb = sidx + 2; if (tb >= 3) tb -= 3;
            uint32_t ab = sb + tb*HG_STAGE, bb = ab + 16384;
            const int k0 = (i+2) << 6;
            #pragma unroll
            for (int j = 0; j < 4; j++) {
                const size_t go = (size_t)(lrow + 32*j) * K + k0 + lch*8;
                CP16(ab + swoff[j], Agp + go);
                CP16(bb + swoff[j], Bgp + go);
            }
        }
        CP_COMMIT();

        const uint32_t As = sb + sidx*HG_STAGE;
        const uint32_t Bs = As + 16384;

        #pragma unroll
        for (int ks = 0; ks < 4; ks++) {
            uint32_t af[4][4], bf[4][2];
            #pragma unroll
            for (int im = 0; im < 4; im++) {
                uint32_t off = SWZ128(a_row0 + (uint32_t)(im*2048) + ks*32 + a_csel);
                LDSM_X4(af[im][0], af[im][1], af[im][2], af[im][3], As + off);
            }
            #pragma unroll
            for (int ntp = 0; ntp < 2; ntp++) {
                uint32_t r0, r1, r2, r3;
                uint32_t off = SWZ128(b_row0 + (uint32_t)(ntp*16*128) + ks*32 + b_csel);
                LDSM_X4(r0, r1, r2, r3, Bs + off);
                bf[2*ntp][0] = r0;  bf[2*ntp][1] = r1;
                bf[2*ntp+1][0] = r2; bf[2*ntp+1][1] = r3;
            }
            #pragma unroll
            for (int im = 0; im < 4; im++)
                #pragma unroll
                for (int in = 0; in < 4; in++)
                    MMA16816(acc[im][in], af[im], bf[in]);
        }
        if (++sidx == 3) sidx = 0;
    }

    const bool dorope = (rc != nullptr) && (bn < KDIM_Q + KDIM_KV);
    const bool doq    = (bn < KDIM_Q);

    #pragma unroll
    for (int im = 0; im < 4; im++) {
        const int ro0 = bm + wm*64 + im*16 + (lane >> 2);
        const int ro1 = ro0 + 8;
        #pragma unroll
        for (int in = 0; in < 4; in++) {
            const int col = bn + wn*32 + in*8 + (lane & 3)*2;
            float a0 = acc[im][in][0], a1 = acc[im][in][1];
            float a2 = acc[im][in][2], a3 = acc[im][in][3];
            if (sizeof(OutT) == 2) {
                if (dorope) {
                    int dcol = col & 127;
                    float c0 = rc[(size_t)ro0*DHEAD + dcol], s0 = rs[(size_t)ro0*DHEAD + dcol];
                    float c1 = rc[(size_t)ro1*DHEAD + dcol], s1 = rs[(size_t)ro1*DHEAD + dcol];
                    float y0 = a0*c0 - a1*s0, y1 = a1*c0 + a0*s0;
                    float y2 = a2*c1 - a3*s1, y3 = a3*c1 + a2*s1;
                    if (doq) { y0 *= QS; y1 *= QS; y2 *= QS; y3 *= QS; }
                    a0 = y0; a1 = y1; a2 = y2; a3 = y3;
                }
                *(__half2*)((__half*)C + (size_t)ro0*ldC + col) = __floats2half2_rn(a0, a1);
                *(__half2*)((__half*)C + (size_t)ro1*ldC + col) = __floats2half2_rn(a2, a3);
            } else {
                float2 v0 = make_float2(a0, a1);
                float2 v1 = make_float2(a2, a3);
                if (R) {
                    const float2 q0 = *(const float2*)&R[(size_t)ro0*ldC + col];
                    const float2 q1 = *(const float2*)&R[(size_t)ro1*ldC + col];
                    v0.x += q0.x; v0.y += q0.y;
                    v1.x += q1.x; v1.y += q1.y;
                }
                *(float2*)((float*)C + (size_t)ro0*ldC + col) = v0;
                *(float2*)((float*)C + (size_t)ro1*ldC + col) = v1;
            }
        }
    }
}

// ============================ HMMA flash attention (causal GQA, pipelined, 2 CTA/SM) ============================
// 1D grid, globally longest-first: head = bid & 31, qt = 31 - (bid >> 5).
// All 32 long (qt=31) tiles dispatch first across heads; qt=0 stubs last (LPT schedule).
#define FA_Q    0
#define FA_KV   16384
#define FA_STG  32768
#define FA_SMEM (FA_KV + 3*FA_STG)   /* 112 KB */

__global__ __launch_bounds__(128) void attn_mma(
    const __half* __restrict__ qkv, __half* __restrict__ out)
{
    extern __shared__ char sm[];
    const uint32_t sb = smem_u32(sm);
    const int tid  = threadIdx.x;
    const int lane = tid & 31;
    const int wid  = tid >> 5;

    const int head = blockIdx.x & (NHEADS - 1);
    const int qt   = (NQT - 1) - (blockIdx.x >> 5);   // longest tiles globally first
    const int kvh  = head >> 2;

    const int lch  = tid & 7;
    const int lr16 = tid >> 3;

    const __half* qg  = qkv + (size_t)(qt*64)*NQKV + head*DHEAD;
    const __half* kg0 = qkv + KDIM_Q + kvh*DHEAD;
    const __half* vg0 = qkv + KDIM_Q + KDIM_KV + kvh*DHEAD;

    const int nkv = qt + 1;

    uint32_t stP = sb + FA_KV + 2*FA_STG;
    uint32_t stC = sb + FA_KV + 0*FA_STG;
    uint32_t stN = sb + FA_KV + 1*FA_STG;
#define FA_ROT() do { uint32_t t_ = stP; stP = stC; stC = stN; stN = t_; } while (0)

#define FA_ISSUE(T, BASE) do { \
    const __half* kg_ = kg0 + (size_t)((T)*64)*NQKV; \
    const __half* vg_ = vg0 + (size_t)((T)*64)*NQKV; \
    _Pragma("unroll") for (int p_ = 0; p_ < 2; p_++) \
    _Pragma("unroll") for (int j_ = 0; j_ < 4; j_++) { \
        int row_ = j_*16 + lr16; \
        uint32_t so_ = SWZ128((uint32_t)(row_*128 + lch*16)); \
        CP16((BASE) + p_*8192 + so_,         kg_ + (size_t)row_*NQKV + p_*64 + lch*8); \
        CP16((BASE) + 16384 + p_*8192 + so_, vg_ + (size_t)row_*NQKV + p_*64 + lch*8); \
    } \
} while (0)

    #pragma unroll
    for (int p = 0; p < 2; p++)
        #pragma unroll
        for (int j = 0; j < 4; j++) {
            int row = j*16 + lr16;
            CP16(sb + FA_Q + p*8192 + SWZ128((uint32_t)(row*128 + lch*16)),
                 qg + (size_t)row*NQKV + p*64 + lch*8);
        }
    FA_ISSUE(0, stC);
    CP_COMMIT();
    CP_WAIT0();
    __syncthreads();

    uint32_t qf[8][4];
    {
        const uint32_t rowb = (uint32_t)(wid*16 + (lane & 15)) * 128;
        const uint32_t csel = (uint32_t)(lane >> 4) * 16;
        #pragma unroll
        for (int ks = 0; ks < 8; ks++) {
            uint32_t addr = sb + FA_Q + (ks >> 2)*8192 + SWZ128(rowb + (ks & 3)*32 + csel);
            LDSM_X4(qf[ks][0], qf[ks][1], qf[ks][2], qf[ks][3], addr);
        }
    }

    float of[16][4];
    #pragma unroll
    for (int t = 0; t < 16; t++)
        #pragma unroll
        for (int r = 0; r < 4; r++) of[t][r] = 0.f;
    float m0 = -1e30f, m1 = -1e30f, l0 = 0.f, l1 = 0.f;
    float sfA[8][4], sfB[8][4];

    const int rg0 = qt*64 + wid*16 + (lane >> 2);
    const uint32_t k_row0 = (uint32_t)(((lane >> 4) & 1)*8 + (lane & 7)) * 128;
    const uint32_t k_csel = (uint32_t)((lane >> 3) & 1) * 16;
    const uint32_t v_rsel = (uint32_t)(lane & 15) * 128;
    const uint32_t v_csel = (uint32_t)(lane >> 4) * 16;

#define FA_SMM(SF, KB) do { \
    _Pragma("unroll") for (int nt_ = 0; nt_ < 8; nt_++) \
        _Pragma("unroll") for (int r_ = 0; r_ < 4; r_++) (SF)[nt_][r_] = 0.f; \
    _Pragma("unroll") for (int ks_ = 0; ks_ < 8; ks_++) { \
        const uint32_t pb_ = (KB) + (ks_ >> 2)*8192; \
        const uint32_t co_ = (ks_ & 3)*32 + k_csel; \
        _Pragma("unroll") for (int ntp_ = 0; ntp_ < 4; ntp_++) { \
            uint32_t x0_, x1_, x2_, x3_; \
            LDSM_X4(x0_, x1_, x2_, x3_, pb_ + SWZ128(k_row0 + (uint32_t)(ntp_*2048) + co_)); \
            uint32_t bA_[2] = {x0_, x1_}, bB_[2] = {x2_, x3_}; \
            MMA16816((SF)[2*ntp_],   qf[ks_], bA_); \
            MMA16816((SF)[2*ntp_+1], qf[ks_], bB_); \
        } \
    } \
} while (0)

#define FA_SMPV(SF, T, VB) do { \
    const bool diag_ = (T) == qt; \
    float mx0_ = -1e30f, mx1_ = -1e30f; \
    _Pragma("unroll") for (int nt_ = 0; nt_ < 8; nt_++) { \
        float s0_ = (SF)[nt_][0], s1_ = (SF)[nt_][1]; \
        float s2_ = (SF)[nt_][2], s3_ = (SF)[nt_][3]; \
        if (diag_) { \
            int cg_ = (T)*64 + nt_*8 + (lane & 3)*2; \
            if (cg_   > rg0)   s0_ = -1e30f; \
            if (cg_+1 > rg0)   s1_ = -1e30f; \
            if (cg_   > rg0+8) s2_ = -1e30f; \
            if (cg_+1 > rg0+8) s3_ = -1e30f; \
        } \
        (SF)[nt_][0] = s0_; (SF)[nt_][1] = s1_; (SF)[nt_][2] = s2_; (SF)[nt_][3] = s3_; \
        mx0_ = fmaxf(mx0_, fmaxf(s0_, s1_)); \
        mx1_ = fmaxf(mx1_, fmaxf(s2_, s3_)); \
    } \
    _Pragma("unroll") for (int o_ = 1; o_ <= 2; o_ <<= 1) { \
        mx0_ = fmaxf(mx0_, __shfl_xor_sync(0xffffffffu, mx0_, o_)); \
        mx1_ = fmaxf(mx1_, __shfl_xor_sync(0xffffffffu, mx1_, o_)); \
    } \
    const float mn0_ = fmaxf(m0, mx0_), mn1_ = fmaxf(m1, mx1_); \
    const float cr0_ = ex2f(m0 - mn0_), cr1_ = ex2f(m1 - mn1_); \
    uint32_t pa0_[8], pa1_[8]; \
    float la0_ = 0.f, la1_ = 0.f; \
    _Pragma("unroll") for (int nt_ = 0; nt_ < 8; nt_++) { \
        float p0_ = ex2f((SF)[nt_][0] - mn0_), p1_ = ex2f((SF)[nt_][1] - mn0_); \
        float p2_ = ex2f((SF)[nt_][2] - mn1_), p3_ = ex2f((SF)[nt_][3] - mn1_); \
        la0_ += p0_ + p1_; la1_ += p2_ + p3_; \
        __half2 h01_ = __floats2half2_rn(p0_, p1_); \
        __half2 h23_ = __floats2half2_rn(p2_, p3_); \
        pa0_[nt_] = *(uint32_t*)&h01_; \
        pa1_[nt_] = *(uint32_t*)&h23_; \
    } \
    _Pragma("unroll") for (int o_ = 1; o_ <= 2; o_ <<= 1) { \
        la0_ += __shfl_xor_sync(0xffffffffu, la0_, o_); \
        la1_ += __shfl_xor_sync(0xffffffffu, la1_, o_); \
    } \
    l0 = l0*cr0_ + la0_;  m0 = mn0_; \
    l1 = l1*cr1_ + la1_;  m1 = mn1_; \
    _Pragma("unroll") for (int t_ = 0; t_ < 16; t_++) { \
        of[t_][0] *= cr0_; of[t_][1] *= cr0_; \
        of[t_][2] *= cr1_; of[t_][3] *= cr1_; \
    } \
    _Pragma("unroll") for (int s_ = 0; s_ < 4; s_++) { \
        uint32_t pfr_[4] = {pa0_[2*s_], pa1_[2*s_], pa0_[2*s_+1], pa1_[2*s_+1]}; \
        _Pragma("unroll") for (int np_ = 0; np_ < 8; np_++) { \
            uint32_t w0_, w1_, w2_, w3_; \
            uint32_t ad_ = (VB) + (np_ >> 2)*8192 + \
                SWZ128((uint32_t)(s_*2048) + v_rsel + (np_ & 3)*32 + v_csel); \
            LDSM_X4T(w0_, w1_, w2_, w3_, ad_); \
            uint32_t vb0_[2] = {w0_, w1_}, vb1_[2] = {w2_, w3_}; \
            MMA16816(of[2*np_],   pfr_, vb0_); \
            MMA16816(of[2*np_+1], pfr_, vb1_); \
        } \
    } \
} while (0)

#define FA_BODY(JT, PROD, CONS, DO_CONS) do { \
    if ((JT) + 1 < nkv) FA_ISSUE((JT) + 1, stN); \
    CP_COMMIT(); \
    FA_SMM(PROD, stC); \
    if (DO_CONS) FA_SMPV(CONS, (JT) - 1, stP + 16384); \
    CP_WAIT0(); \
    __syncthreads(); \
} while (0)

    FA_BODY(0, sfA, sfB, false); FA_ROT();
    int jt = 1;
    for (; jt + 1 < nkv; jt += 2) {
        FA_BODY(jt,   sfB, sfA, true); FA_ROT();
        FA_BODY(jt+1, sfA, sfB, true); FA_ROT();
    }
    if (jt < nkv) {
        FA_BODY(jt, sfB, sfA, true); FA_ROT();
        FA_SMPV(sfB, nkv-1, stP + 16384);
    } else {
        FA_SMPV(sfA, nkv-1, stP + 16384);
    }

    const float il0 = 1.f / l0, il1 = 1.f / l1;
    __half* ob = out + (size_t)(qt*64 + wid*16 + (lane >> 2))*DMODEL + head*DHEAD + (lane & 3)*2;
    #pragma unroll
    for (int t = 0; t < 16; t++) {
        *(__half2*)(ob + t*8)            = __floats2half2_rn(of[t][0]*il0, of[t][1]*il0);
        *(__half2*)(ob + 8*DMODEL + t*8) = __floats2half2_rn(of[t][2]*il1, of[t][3]*il1);
    }
}

// ============================ launch ============================
extern "C" void kernel_launch(void* const* d_in, const int* in_sizes, int n_in,
                              void* d_out, int out_size)
{
    const float* x     = (const float*)d_in[0];
    const float* r_cos = (const float*)d_in[1];
    const float* r_sin = (const float*)d_in[2];
    /* d_in[3] mask: causal, implemented analytically */
    const float* nw    = (const float*)d_in[4];
    const float* wq    = (const float*)d_in[5];
    const float* wk    = (const float*)d_in[6];
    const float* wv    = (const float*)d_in[7];
    const float* wo    = (const float*)d_in[8];
    float* out = (float*)d_out;

    __half *h16, *wqkv16, *wo16, *qkv16, *attn16;
    cudaGetSymbolAddress((void**)&h16,    g_h16);
    cudaGetSymbolAddress((void**)&wqkv16, g_wqkv16);
    cudaGetSymbolAddress((void**)&wo16,   g_wo16);
    cudaGetSymbolAddress((void**)&qkv16,  g_qkv16);
    cudaGetSymbolAddress((void**)&attn16, g_attn16);

    cudaFuncSetAttribute(hgemm_mma<float>,  cudaFuncAttributeMaxDynamicSharedMemorySize, HG_SMEM);
    cudaFuncSetAttribute(hgemm_mma<__half>, cudaFuncAttributeMaxDynamicSharedMemorySize, HG_SMEM);
    cudaFuncSetAttribute(attn_mma,          cudaFuncAttributeMaxDynamicSharedMemorySize, FA_SMEM);

    // 1. fused prep: weight conversion + RMSNorm
    prep_kernel<<<NCVT + SQ, 256>>>((const float4*)wq, (const float4*)wk,
                                    (const float4*)wv, (const float4*)wo,
                                    (__half2*)wqkv16, (__half2*)wo16,
                                    x, nw, h16);

    // 2. fused QKV projection + RoPE + Q prescale (HMMA, fp16 out)
    hgemm_mma<__half><<<dim3(NQKV/128, SQ/128), 256, HG_SMEM>>>(
        h16, wqkv16, qkv16, nullptr, SQ, NQKV, DMODEL, NQKV, r_cos, r_sin);

    // 3. causal GQA flash attention (HMMA, globally longest-first 1D grid)
    attn_mma<<<NQT * NHEADS, 128, FA_SMEM>>>(qkv16, attn16);

    // 4. output projection + residual (HMMA, fp32 out)
    hgemm_mma<float><<<dim3(DMODEL/128, SQ/128), 256, HG_SMEM>>>(
        attn16, wo16, out, x, SQ, DMODEL, DMODEL, DMODEL, nullptr, nullptr);
}